// round 3
// baseline (speedup 1.0000x reference)
#include <cuda_runtime.h>
#include <cuda_bf16.h>
#include <math.h>

#define Lt 256
#define Li 2048
#define LL 2304          // Lt + Li
#define DD 2048
#define HH 16
#define HD 128
#define MLPD 8192
#define EPSF 1e-6f

// ---------------- scratch (static device globals; no allocation) ----------------
__device__ __align__(16) float g_sv[DD];
__device__ __align__(16) float g_mod_img[6 * DD];
__device__ __align__(16) float g_mod_txt[6 * DD];
__device__ __align__(16) float g_modx_img[Li * DD];
__device__ __align__(16) float g_modx_txt[Lt * DD];
__device__ __align__(16) float g_qkv_img[Li * 3 * DD];
__device__ __align__(16) float g_qkv_txt[Lt * 3 * DD];
__device__ __align__(16) float g_q[HH * LL * HD];
__device__ __align__(16) float g_k[HH * LL * HD];
__device__ __align__(16) float g_v[HH * LL * HD];
__device__ __align__(16) float g_scores[LL * LL];
__device__ __align__(16) float g_attnout[LL * DD];
__device__ __align__(16) float g_res_img[Li * DD];
__device__ __align__(16) float g_res_txt[Lt * DD];
__device__ __align__(16) float g_h[Li * DD];
__device__ __align__(16) float g_mlp[Li * MLPD];

// ---------------- small kernels ----------------
__global__ void silu_k(const float* __restrict__ vec, float* __restrict__ sv) {
    int i = blockIdx.x * blockDim.x + threadIdx.x;
    if (i < DD) {
        float x = vec[i];
        sv[i] = x / (1.0f + __expf(-x));
    }
}

// out[j] = sum_d sv[d] * W[d][j] + b[j]   (W: (D, 6D) row-major)
__global__ void modmul_k(const float* __restrict__ sv, const float* __restrict__ W,
                         const float* __restrict__ b, float* __restrict__ out) {
    __shared__ float s[DD];
    for (int i = threadIdx.x; i < DD; i += 128) s[i] = sv[i];
    __syncthreads();
    int j = blockIdx.x * 128 + threadIdx.x;
    float acc = 0.0f;
    const float* wp = W + j;
    for (int d = 0; d < DD; d++) acc += s[d] * wp[(size_t)d * (6 * DD)];
    out[j] = acc + b[j];
}

// y = (1+sc[c]) * layernorm(x_row) + sh[c]
__global__ void ln_mod_k(const float* __restrict__ x, float* __restrict__ y,
                         const float* __restrict__ sh, const float* __restrict__ sc) {
    int row = blockIdx.x;
    const float* px = x + (size_t)row * DD;
    float* py = y + (size_t)row * DD;
    __shared__ float red[256];
    int tid = threadIdx.x;
    float v[8];
    float s = 0.0f;
#pragma unroll
    for (int i = 0; i < 8; i++) { v[i] = px[tid + i * 256]; s += v[i]; }
    red[tid] = s; __syncthreads();
    for (int o = 128; o > 0; o >>= 1) { if (tid < o) red[tid] += red[tid + o]; __syncthreads(); }
    float mu = red[0] * (1.0f / DD);
    __syncthreads();
    float ss = 0.0f;
#pragma unroll
    for (int i = 0; i < 8; i++) { float d = v[i] - mu; ss += d * d; }
    red[tid] = ss; __syncthreads();
    for (int o = 128; o > 0; o >>= 1) { if (tid < o) red[tid] += red[tid + o]; __syncthreads(); }
    float r = rsqrtf(red[0] * (1.0f / DD) + EPSF);
#pragma unroll
    for (int i = 0; i < 8; i++) {
        int c = tid + i * 256;
        py[c] = (1.0f + sc[c]) * ((v[i] - mu) * r) + sh[c];
    }
}

// split qkv, rmsnorm(q,k) * scale, rope(q,k), scatter to (H, L, HD) layout; txt first
__global__ void qkv_prep_k(const float* __restrict__ qkv_txt, const float* __restrict__ qkv_img,
                           const float* __restrict__ tq_s, const float* __restrict__ tk_s,
                           const float* __restrict__ iq_s, const float* __restrict__ ik_s,
                           const float* __restrict__ pe,
                           float* __restrict__ q, float* __restrict__ k, float* __restrict__ v) {
    int h = blockIdx.x;
    int pos = blockIdx.y;
    int d = threadIdx.x;
    const float* src; int l; const float* qs; const float* ks;
    if (pos < Lt) { src = qkv_txt; l = pos;       qs = tq_s; ks = tk_s; }
    else          { src = qkv_img; l = pos - Lt;  qs = iq_s; ks = ik_s; }
    const float* base = src + (size_t)l * (3 * DD) + h * HD;
    float qv = base[d];
    float kv = base[DD + d];
    float vv = base[2 * DD + d];

    __shared__ float sq[HD], sk[HD], red[8];
    float q2 = qv * qv, k2 = kv * kv;
#pragma unroll
    for (int o = 16; o > 0; o >>= 1) {
        q2 += __shfl_xor_sync(0xFFFFFFFFu, q2, o);
        k2 += __shfl_xor_sync(0xFFFFFFFFu, k2, o);
    }
    int w = d >> 5;
    if ((d & 31) == 0) { red[w] = q2; red[4 + w] = k2; }
    __syncthreads();
    float qss = red[0] + red[1] + red[2] + red[3];
    float kss = red[4] + red[5] + red[6] + red[7];
    float qn = qv * rsqrtf(qss * (1.0f / HD) + EPSF) * qs[d];
    float kn = kv * rsqrtf(kss * (1.0f / HD) + EPSF) * ks[d];
    sq[d] = qn; sk[d] = kn;
    __syncthreads();
    int i = d >> 1, j = d & 1;
    const float* pp = pe + (((size_t)pos * 64 + i) * 4 + j * 2);
    float p0 = pp[0], p1 = pp[1];
    float x0q = sq[2 * i], x1q = sq[2 * i + 1];
    float x0k = sk[2 * i], x1k = sk[2 * i + 1];
    size_t o = ((size_t)h * LL + pos) * HD + d;
    q[o] = p0 * x0q + p1 * x1q;
    k[o] = p0 * x0k + p1 * x1k;
    v[o] = vv;
}

__global__ void softmax_k(float* __restrict__ s, int ncols) {
    int row = blockIdx.x;
    float* p = s + (size_t)row * ncols;
    __shared__ float red[256];
    int tid = threadIdx.x;
    float m = -1e30f;
    for (int c = tid; c < ncols; c += 256) m = fmaxf(m, p[c]);
    red[tid] = m; __syncthreads();
    for (int o = 128; o > 0; o >>= 1) { if (tid < o) red[tid] = fmaxf(red[tid], red[tid + o]); __syncthreads(); }
    m = red[0]; __syncthreads();
    float sum = 0.0f;
    for (int c = tid; c < ncols; c += 256) { float e = __expf(p[c] - m); p[c] = e; sum += e; }
    red[tid] = sum; __syncthreads();
    for (int o = 128; o > 0; o >>= 1) { if (tid < o) red[tid] += red[tid + o]; __syncthreads(); }
    float inv = 1.0f / red[0];
    for (int c = tid; c < ncols; c += 256) p[c] *= inv;
}

// ---------------- tiled SGEMM with fused epilogues ----------------
// EPI 0: C = alpha * (A@B)
// EPI 2: C = res + gate[col] * (A@B + bias[col])
// EPI 3: C = gelu_tanh(A@B + bias[col])
// TRANSB: B given as (N, K) row-major (computes A @ B^T)
#define BM 128
#define BN 128
#define BK 8
template <int EPI, bool TRANSB>
__global__ __launch_bounds__(256) void gemm_k(
    const float* __restrict__ A, const float* __restrict__ B, float* __restrict__ C,
    int M, int N, int K, int lda, int ldb, int ldc, float alpha,
    const float* __restrict__ bias, const float* __restrict__ gate,
    const float* __restrict__ res, int ldres) {
    __shared__ float As[BK][BM];
    __shared__ float Bs[BK][BN];
    int tid = threadIdx.x;
    int tx = tid & 15, ty = tid >> 4;
    int m0 = blockIdx.y * BM, n0 = blockIdx.x * BN;
    float acc[8][8] = {};
    int a_m = tid >> 1;
    int a_k = (tid & 1) * 4;
    int b_k, b_n;
    if (!TRANSB) { b_k = tid >> 5; b_n = (tid & 31) * 4; }
    else         { b_n = tid >> 1; b_k = (tid & 1) * 4; }

    for (int k0 = 0; k0 < K; k0 += BK) {
        float4 av = *(const float4*)&A[(size_t)(m0 + a_m) * lda + k0 + a_k];
        As[a_k + 0][a_m] = av.x; As[a_k + 1][a_m] = av.y;
        As[a_k + 2][a_m] = av.z; As[a_k + 3][a_m] = av.w;
        if (!TRANSB) {
            *(float4*)&Bs[b_k][b_n] = *(const float4*)&B[(size_t)(k0 + b_k) * ldb + n0 + b_n];
        } else {
            float4 bv = *(const float4*)&B[(size_t)(n0 + b_n) * ldb + k0 + b_k];
            Bs[b_k + 0][b_n] = bv.x; Bs[b_k + 1][b_n] = bv.y;
            Bs[b_k + 2][b_n] = bv.z; Bs[b_k + 3][b_n] = bv.w;
        }
        __syncthreads();
#pragma unroll
        for (int kk = 0; kk < BK; kk++) {
            float a[8], b[8];
            *(float4*)(a)     = *(const float4*)&As[kk][ty * 8];
            *(float4*)(a + 4) = *(const float4*)&As[kk][ty * 8 + 4];
            *(float4*)(b)     = *(const float4*)&Bs[kk][tx * 8];
            *(float4*)(b + 4) = *(const float4*)&Bs[kk][tx * 8 + 4];
#pragma unroll
            for (int i = 0; i < 8; i++)
#pragma unroll
                for (int j = 0; j < 8; j++) acc[i][j] += a[i] * b[j];
        }
        __syncthreads();
    }
#pragma unroll
    for (int i = 0; i < 8; i++) {
        int row = m0 + ty * 8 + i;
#pragma unroll
        for (int j = 0; j < 8; j++) {
            int col = n0 + tx * 8 + j;
            float vv = acc[i][j];
            if (EPI == 0) {
                vv *= alpha;
            } else if (EPI == 2) {
                vv = res[(size_t)row * ldres + col] + gate[col] * (vv + bias[col]);
            } else if (EPI == 3) {
                vv += bias[col];
                float x3 = vv * vv * vv;
                vv = 0.5f * vv * (1.0f + tanhf(0.7978845608028654f * (vv + 0.044715f * x3)));
            }
            C[(size_t)row * ldc + col] = vv;
        }
    }
}

// ---------------- host side ----------------
#define SYM(p, s) do { void* _t = nullptr; cudaGetSymbolAddress(&_t, s); (p) = (float*)_t; } while (0)

extern "C" void kernel_launch(void* const* d_in, const int* in_sizes, int n_in,
                              void* d_out, int out_size) {
    const float* img     = (const float*)d_in[0];
    const float* txt     = (const float*)d_in[1];
    const float* vec     = (const float*)d_in[2];
    const float* pe      = (const float*)d_in[3];
    const float* i_mod_w = (const float*)d_in[4];
    const float* i_mod_b = (const float*)d_in[5];
    const float* i_qkv_w = (const float*)d_in[6];
    const float* i_q_s   = (const float*)d_in[7];
    const float* i_k_s   = (const float*)d_in[8];
    const float* i_pw    = (const float*)d_in[9];
    const float* i_pb    = (const float*)d_in[10];
    const float* i_w1    = (const float*)d_in[11];
    const float* i_b1    = (const float*)d_in[12];
    const float* i_w2    = (const float*)d_in[13];
    const float* i_b2    = (const float*)d_in[14];
    const float* t_mod_w = (const float*)d_in[15];
    const float* t_mod_b = (const float*)d_in[16];
    const float* t_qkv_w = (const float*)d_in[17];
    const float* t_q_s   = (const float*)d_in[18];
    const float* t_k_s   = (const float*)d_in[19];
    const float* t_pw    = (const float*)d_in[20];
    const float* t_pb    = (const float*)d_in[21];
    const float* t_w1    = (const float*)d_in[22];
    const float* t_b1    = (const float*)d_in[23];
    const float* t_w2    = (const float*)d_in[24];
    const float* t_b2    = (const float*)d_in[25];

    float* out_img = (float*)d_out;
    float* out_txt = out_img + (size_t)Li * DD;

    float *sv, *mod_i, *mod_t, *modx_i, *modx_t, *qkv_i, *qkv_t;
    float *qb, *kb, *vb, *sc, *ao, *res_i, *res_t, *hb, *mb;
    SYM(sv, g_sv); SYM(mod_i, g_mod_img); SYM(mod_t, g_mod_txt);
    SYM(modx_i, g_modx_img); SYM(modx_t, g_modx_txt);
    SYM(qkv_i, g_qkv_img); SYM(qkv_t, g_qkv_txt);
    SYM(qb, g_q); SYM(kb, g_k); SYM(vb, g_v);
    SYM(sc, g_scores); SYM(ao, g_attnout);
    SYM(res_i, g_res_img); SYM(res_t, g_res_txt);
    SYM(hb, g_h); SYM(mb, g_mlp);

    // 1. modulation
    silu_k<<<(DD + 255) / 256, 256>>>(vec, sv);
    modmul_k<<<6 * DD / 128, 128>>>(sv, i_mod_w, i_mod_b, mod_i);
    modmul_k<<<6 * DD / 128, 128>>>(sv, t_mod_w, t_mod_b, mod_t);

    // 2. LN1 + modulate
    ln_mod_k<<<Li, 256>>>(img, modx_i, mod_i + 0 * DD, mod_i + 1 * DD);
    ln_mod_k<<<Lt, 256>>>(txt, modx_t, mod_t + 0 * DD, mod_t + 1 * DD);

    // 3. qkv GEMMs
    gemm_k<0, false><<<dim3(3 * DD / BN, Li / BM), 256>>>(
        modx_i, i_qkv_w, qkv_i, Li, 3 * DD, DD, DD, 3 * DD, 3 * DD, 1.0f, nullptr, nullptr, nullptr, 0);
    gemm_k<0, false><<<dim3(3 * DD / BN, Lt / BM), 256>>>(
        modx_t, t_qkv_w, qkv_t, Lt, 3 * DD, DD, DD, 3 * DD, 3 * DD, 1.0f, nullptr, nullptr, nullptr, 0);

    // 4. split + rmsnorm + rope
    qkv_prep_k<<<dim3(HH, LL), HD>>>(qkv_t, qkv_i, t_q_s, t_k_s, i_q_s, i_k_s, pe, qb, kb, vb);

    // 5. attention per head
    const float iscale = 0.08838834764831845f; // 1/sqrt(128)
    for (int h = 0; h < HH; h++) {
        const float* qh = qb + (size_t)h * LL * HD;
        const float* kh = kb + (size_t)h * LL * HD;
        const float* vh = vb + (size_t)h * LL * HD;
        gemm_k<0, true><<<dim3(LL / BN, LL / BM), 256>>>(
            qh, kh, sc, LL, LL, HD, HD, HD, LL, iscale, nullptr, nullptr, nullptr, 0);
        softmax_k<<<LL, 256>>>(sc, LL);
        gemm_k<0, false><<<dim3(HD / BN, LL / BM), 256>>>(
            sc, vh, ao + h * HD, LL, HD, LL, LL, HD, DD, 1.0f, nullptr, nullptr, nullptr, 0);
    }

    // 6. proj + gated residual
    gemm_k<2, false><<<dim3(DD / BN, Li / BM), 256>>>(
        ao + (size_t)Lt * DD, i_pw, res_i, Li, DD, DD, DD, DD, DD, 1.0f, i_pb, mod_i + 2 * DD, img, DD);
    gemm_k<2, false><<<dim3(DD / BN, Lt / BM), 256>>>(
        ao, t_pw, res_t, Lt, DD, DD, DD, DD, DD, 1.0f, t_pb, mod_t + 2 * DD, txt, DD);

    // 7. img MLP
    ln_mod_k<<<Li, 256>>>(res_i, hb, mod_i + 3 * DD, mod_i + 4 * DD);
    gemm_k<3, false><<<dim3(MLPD / BN, Li / BM), 256>>>(
        hb, i_w1, mb, Li, MLPD, DD, DD, MLPD, MLPD, 1.0f, i_b1, nullptr, nullptr, 0);
    gemm_k<2, false><<<dim3(DD / BN, Li / BM), 256>>>(
        mb, i_w2, out_img, Li, DD, MLPD, MLPD, DD, DD, 1.0f, i_b2, mod_i + 5 * DD, res_i, DD);

    // 8. txt MLP
    ln_mod_k<<<Lt, 256>>>(res_t, hb, mod_t + 3 * DD, mod_t + 4 * DD);
    gemm_k<3, false><<<dim3(MLPD / BN, Lt / BM), 256>>>(
        hb, t_w1, mb, Lt, MLPD, DD, DD, MLPD, MLPD, 1.0f, t_b1, nullptr, nullptr, 0);
    gemm_k<2, false><<<dim3(DD / BN, Lt / BM), 256>>>(
        mb, t_w2, out_txt, Lt, DD, MLPD, MLPD, DD, DD, 1.0f, t_b2, mod_t + 5 * DD, res_t, DD);

    (void)in_sizes; (void)n_in; (void)out_size;
}

// round 5
// speedup vs baseline: 3.8831x; 3.8831x over previous
#include <cuda_runtime.h>
#include <cuda_bf16.h>
#include <math.h>
#include <stdint.h>

#define Lt 256
#define Li 2048
#define LL 2304          // Lt + Li
#define DD 2048
#define HH 16
#define HD 128
#define MLPD 8192
#define EPSF 1e-6f

// ================= helpers =================
__device__ __forceinline__ uint32_t smem_to_u32(const void* p) {
    uint32_t a;
    asm("{ .reg .u64 t; cvta.to.shared.u64 t, %1; cvt.u32.u64 %0, t; }" : "=r"(a) : "l"(p));
    return a;
}
__device__ __forceinline__ void cpa16(uint32_t dst, const void* src) {
    asm volatile("cp.async.cg.shared.global [%0], [%1], 16;" :: "r"(dst), "l"(src));
}
#define CP_COMMIT() asm volatile("cp.async.commit_group;" ::: "memory")
#define CP_WAIT(N)  asm volatile("cp.async.wait_group %0;" :: "n"(N) : "memory")

__device__ __forceinline__ void ldsm_x4(uint32_t addr, uint32_t* r) {
    asm volatile("ldmatrix.sync.aligned.m8n8.x4.shared.b16 {%0,%1,%2,%3}, [%4];"
                 : "=r"(r[0]), "=r"(r[1]), "=r"(r[2]), "=r"(r[3]) : "r"(addr));
}
__device__ __forceinline__ void ldsm_x2(uint32_t addr, uint32_t* r) {
    asm volatile("ldmatrix.sync.aligned.m8n8.x2.shared.b16 {%0,%1}, [%2];"
                 : "=r"(r[0]), "=r"(r[1]) : "r"(addr));
}
__device__ __forceinline__ void mma_bf16(float* d, const uint32_t* a, const uint32_t* b) {
    asm volatile(
        "mma.sync.aligned.m16n8k16.row.col.f32.bf16.bf16.f32 "
        "{%0,%1,%2,%3}, {%4,%5,%6,%7}, {%8,%9}, {%0,%1,%2,%3};"
        : "+f"(d[0]), "+f"(d[1]), "+f"(d[2]), "+f"(d[3])
        : "r"(a[0]), "r"(a[1]), "r"(a[2]), "r"(a[3]), "r"(b[0]), "r"(b[1]));
}

__device__ __forceinline__ void split2(float x, __nv_bfloat16& h, __nv_bfloat16& l) {
    h = __float2bfloat16(x);
    l = __float2bfloat16(x - __bfloat162float(h));
}
__device__ __forceinline__ float gelu_tanh(float x) {
    float x3 = x * x * x;
    return 0.5f * x * (1.0f + tanhf(0.7978845608028654f * (x + 0.044715f * x3)));
}

// ================= scratch (static device globals) =================
__device__ __align__(16) float g_sv[DD];
__device__ __align__(16) float g_mod_img[6 * DD];
__device__ __align__(16) float g_mod_txt[6 * DD];
__device__ __align__(16) __nv_bfloat16 g_mxi_h[Li * DD];
__device__ __align__(16) __nv_bfloat16 g_mxi_l[Li * DD];
__device__ __align__(16) __nv_bfloat16 g_mxt_h[Lt * DD];
__device__ __align__(16) __nv_bfloat16 g_mxt_l[Lt * DD];
__device__ __align__(16) __nv_bfloat16 g_wt_h[MLPD * DD];   // reusable transposed weight (hi)
__device__ __align__(16) __nv_bfloat16 g_wt_l[MLPD * DD];   // reusable transposed weight (lo)
__device__ __align__(16) float g_qkv_img[Li * 3 * DD];
__device__ __align__(16) float g_qkv_txt[Lt * 3 * DD];
__device__ __align__(16) __nv_bfloat16 g_qh[HH * LL * HD];
__device__ __align__(16) __nv_bfloat16 g_ql[HH * LL * HD];
__device__ __align__(16) __nv_bfloat16 g_kh[HH * LL * HD];
__device__ __align__(16) __nv_bfloat16 g_kl[HH * LL * HD];
__device__ __align__(16) __nv_bfloat16 g_vth[HH * HD * LL]; // V transposed per head
__device__ __align__(16) __nv_bfloat16 g_vtl[HH * HD * LL];
__device__ __align__(16) float g_scores[(size_t)HH * LL * LL];
__device__ __align__(16) __nv_bfloat16 g_ph[(size_t)HH * LL * LL];
__device__ __align__(16) __nv_bfloat16 g_pl[(size_t)HH * LL * LL];
__device__ __align__(16) float g_ao[LL * DD];
__device__ __align__(16) __nv_bfloat16 g_aoh[LL * DD];
__device__ __align__(16) __nv_bfloat16 g_aol[LL * DD];
__device__ __align__(16) float g_res_i[Li * DD];
__device__ __align__(16) float g_res_t[Lt * DD];
__device__ __align__(16) __nv_bfloat16 g_hh[Li * DD];
__device__ __align__(16) __nv_bfloat16 g_hl[Li * DD];
__device__ __align__(16) __nv_bfloat16 g_mh[(size_t)Li * MLPD];
__device__ __align__(16) __nv_bfloat16 g_ml[(size_t)Li * MLPD];

// ================= small kernels =================
__global__ void silu_k(const float* __restrict__ vec, float* __restrict__ sv) {
    int i = blockIdx.x * blockDim.x + threadIdx.x;
    if (i < DD) { float x = vec[i]; sv[i] = x / (1.0f + __expf(-x)); }
}

__global__ void modmul_k(const float* __restrict__ sv, const float* __restrict__ W,
                         const float* __restrict__ b, float* __restrict__ out) {
    __shared__ float s[DD];
    for (int i = threadIdx.x; i < DD; i += 128) s[i] = sv[i];
    __syncthreads();
    int j = blockIdx.x * 128 + threadIdx.x;
    float acc = 0.0f;
    const float* wp = W + j;
    for (int d = 0; d < DD; d++) acc += s[d] * wp[(size_t)d * (6 * DD)];
    out[j] = acc + b[j];
}

// y_hi/y_lo = split((1+sc)*LN(x) + sh)
__global__ void ln_mod_split_k(const float* __restrict__ x,
                               __nv_bfloat16* __restrict__ yh, __nv_bfloat16* __restrict__ yl,
                               const float* __restrict__ sh, const float* __restrict__ sc) {
    int row = blockIdx.x;
    const float* px = x + (size_t)row * DD;
    __shared__ float red[256];
    int tid = threadIdx.x;
    float v[8];
    float s = 0.0f;
#pragma unroll
    for (int i = 0; i < 8; i++) { v[i] = px[tid + i * 256]; s += v[i]; }
    red[tid] = s; __syncthreads();
    for (int o = 128; o > 0; o >>= 1) { if (tid < o) red[tid] += red[tid + o]; __syncthreads(); }
    float mu = red[0] * (1.0f / DD);
    __syncthreads();
    float ss = 0.0f;
#pragma unroll
    for (int i = 0; i < 8; i++) { float d = v[i] - mu; ss += d * d; }
    red[tid] = ss; __syncthreads();
    for (int o = 128; o > 0; o >>= 1) { if (tid < o) red[tid] += red[tid + o]; __syncthreads(); }
    float r = rsqrtf(red[0] * (1.0f / DD) + EPSF);
#pragma unroll
    for (int i = 0; i < 8; i++) {
        int c = tid + i * 256;
        float y = (1.0f + sc[c]) * ((v[i] - mu) * r) + sh[c];
        __nv_bfloat16 h, l; split2(y, h, l);
        yh[(size_t)row * DD + c] = h;
        yl[(size_t)row * DD + c] = l;
    }
}

// transpose + split: W[K,N] fp32 -> Wt_hi/lo [N,K] bf16
__global__ void wconv_k(const float* __restrict__ W,
                        __nv_bfloat16* __restrict__ Wh, __nv_bfloat16* __restrict__ Wl,
                        int Kd, int Nd) {
    __shared__ float t[32][33];
    int n = blockIdx.x * 32 + threadIdx.x;
#pragma unroll
    for (int i = 0; i < 4; i++) {
        int k = blockIdx.y * 32 + threadIdx.y + i * 8;
        t[threadIdx.y + i * 8][threadIdx.x] = W[(size_t)k * Nd + n];
    }
    __syncthreads();
    int k2 = blockIdx.y * 32 + threadIdx.x;
#pragma unroll
    for (int i = 0; i < 4; i++) {
        int n2 = blockIdx.x * 32 + threadIdx.y + i * 8;
        float v = t[threadIdx.x][threadIdx.y + i * 8];
        __nv_bfloat16 h, l; split2(v, h, l);
        Wh[(size_t)n2 * Kd + k2] = h;
        Wl[(size_t)n2 * Kd + k2] = l;
    }
}

// generic fp32 -> hi/lo bf16 split
__global__ void split_k(const float* __restrict__ x,
                        __nv_bfloat16* __restrict__ h, __nv_bfloat16* __restrict__ l, size_t n) {
    size_t i = (size_t)blockIdx.x * blockDim.x + threadIdx.x;
    if (i < n) { __nv_bfloat16 a, b; split2(x[i], a, b); h[i] = a; l[i] = b; }
}

// split qkv, rmsnorm(q,k)*scale, rope(q,k) -> hi/lo bf16 (q,k [H,L,HD]; v transposed [H,HD,L])
__global__ void qkv_prep_k(const float* __restrict__ qkv_txt, const float* __restrict__ qkv_img,
                           const float* __restrict__ tq_s, const float* __restrict__ tk_s,
                           const float* __restrict__ iq_s, const float* __restrict__ ik_s,
                           const float* __restrict__ pe,
                           __nv_bfloat16* __restrict__ qh, __nv_bfloat16* __restrict__ ql,
                           __nv_bfloat16* __restrict__ kh, __nv_bfloat16* __restrict__ kl,
                           __nv_bfloat16* __restrict__ vth, __nv_bfloat16* __restrict__ vtl) {
    int h = blockIdx.x;
    int pos = blockIdx.y;
    int d = threadIdx.x;
    const float* src; int l; const float* qs; const float* ks;
    if (pos < Lt) { src = qkv_txt; l = pos;      qs = tq_s; ks = tk_s; }
    else          { src = qkv_img; l = pos - Lt; qs = iq_s; ks = ik_s; }
    const float* base = src + (size_t)l * (3 * DD) + h * HD;
    float qv = base[d];
    float kv = base[DD + d];
    float vv = base[2 * DD + d];

    __shared__ float sq[HD], sk[HD], red[8];
    float q2 = qv * qv, k2 = kv * kv;
#pragma unroll
    for (int o = 16; o > 0; o >>= 1) {
        q2 += __shfl_xor_sync(0xFFFFFFFFu, q2, o);
        k2 += __shfl_xor_sync(0xFFFFFFFFu, k2, o);
    }
    int w = d >> 5;
    if ((d & 31) == 0) { red[w] = q2; red[4 + w] = k2; }
    __syncthreads();
    float qss = red[0] + red[1] + red[2] + red[3];
    float kss = red[4] + red[5] + red[6] + red[7];
    float qn = qv * rsqrtf(qss * (1.0f / HD) + EPSF) * qs[d];
    float kn = kv * rsqrtf(kss * (1.0f / HD) + EPSF) * ks[d];
    sq[d] = qn; sk[d] = kn;
    __syncthreads();
    int i = d >> 1, j = d & 1;
    const float* pp = pe + (((size_t)pos * 64 + i) * 4 + j * 2);
    float p0 = pp[0], p1 = pp[1];
    float rq = p0 * sq[2 * i] + p1 * sq[2 * i + 1];
    float rk = p0 * sk[2 * i] + p1 * sk[2 * i + 1];
    size_t o = ((size_t)h * LL + pos) * HD + d;
    __nv_bfloat16 a, b;
    split2(rq, a, b); qh[o] = a; ql[o] = b;
    split2(rk, a, b); kh[o] = a; kl[o] = b;
    size_t ov = ((size_t)h * HD + d) * LL + pos;
    split2(vv, a, b); vth[ov] = a; vtl[ov] = b;
}

// softmax over rows (in-place exp on scores), write hi/lo bf16 probs
__global__ void softmax_split_k(float* __restrict__ s,
                                __nv_bfloat16* __restrict__ ph, __nv_bfloat16* __restrict__ pl,
                                int ncols) {
    size_t row = blockIdx.x;
    float* p = s + row * ncols;
    __shared__ float red[256];
    int tid = threadIdx.x;
    float m = -1e30f;
    for (int c = tid; c < ncols; c += 256) m = fmaxf(m, p[c]);
    red[tid] = m; __syncthreads();
    for (int o = 128; o > 0; o >>= 1) { if (tid < o) red[tid] = fmaxf(red[tid], red[tid + o]); __syncthreads(); }
    m = red[0]; __syncthreads();
    float sum = 0.0f;
    for (int c = tid; c < ncols; c += 256) { float e = __expf(p[c] - m); p[c] = e; sum += e; }
    red[tid] = sum; __syncthreads();
    for (int o = 128; o > 0; o >>= 1) { if (tid < o) red[tid] += red[tid + o]; __syncthreads(); }
    float inv = 1.0f / red[0];
    for (int c = tid; c < ncols; c += 256) {
        float v = p[c] * inv;
        __nv_bfloat16 a, b; split2(v, a, b);
        ph[row * ncols + c] = a; pl[row * ncols + c] = b;
    }
}

// ================= HMMA (mma.sync bf16) GEMM =================
// C[M,N] = epi( (Ah+Al)[M,K] @ (Bh+Bl)[N,K]^T ), 3-product hi/lo split, fp32 accum.
// CTA tile 128x128, BK=32. 8 warps (2x4), warp tile 64x32, mma m16n8k16.
// SMEM per stage: 4 arrays (Ah,Al,Bh,Bl), each 128 rows x 40 bf16 (80B stride).
// cp.async double buffering.
#define SROW 80                       // bytes per smem row
#define ARRB (128 * SROW)             // 10240 bytes per array
#define STAGEB (4 * ARRB)             // 40960 bytes per stage
#define TGEMM_SMEM (2 * STAGEB)       // 81920

template <int EPI>
__global__ __launch_bounds__(256, 1) void tgemm(
    const __nv_bfloat16* __restrict__ Ah, const __nv_bfloat16* __restrict__ Al, long long sAz,
    const __nv_bfloat16* __restrict__ Bh, const __nv_bfloat16* __restrict__ Bl, long long sBz,
    float* __restrict__ C, long long sCz,
    __nv_bfloat16* __restrict__ Chi, __nv_bfloat16* __restrict__ Clo,
    int K, int lda, int ldb, int ldc, float alpha,
    const float* __restrict__ bias, const float* __restrict__ gate,
    const float* __restrict__ res, int ldres) {
    extern __shared__ char smem[];
    uint32_t sb = smem_to_u32(smem);
    int tid = threadIdx.x, wid = tid >> 5, lane = tid & 31;
    int warpM = wid >> 2, warpN = wid & 3;
    int m0 = blockIdx.y * 128, n0 = blockIdx.x * 128;
    int z = blockIdx.z;
    Ah += (size_t)z * sAz; Al += (size_t)z * sAz;
    Bh += (size_t)z * sBz; Bl += (size_t)z * sBz;
    if (C)   C   += (size_t)z * sCz;
    if (Chi) { Chi += (size_t)z * sCz; Clo += (size_t)z * sCz; }

    const __nv_bfloat16* g0 = Ah + (size_t)m0 * lda;
    const __nv_bfloat16* g1 = Al + (size_t)m0 * lda;
    const __nv_bfloat16* g2 = Bh + (size_t)n0 * ldb;
    const __nv_bfloat16* g3 = Bl + (size_t)n0 * ldb;

    int r0 = tid >> 2, q0 = tid & 3;          // chunk 0: rows 0..63
    int r1 = (tid + 256) >> 2, q1 = q0;       // chunk 1: rows 64..127
    uint32_t d00 = sb + r0 * SROW + q0 * 16;
    uint32_t d01 = sb + r1 * SROW + q1 * 16;

    float acc[4][4][4];
#pragma unroll
    for (int i = 0; i < 4; i++)
#pragma unroll
        for (int j = 0; j < 4; j++)
#pragma unroll
            for (int f = 0; f < 4; f++) acc[i][j][f] = 0.0f;

    int nit = K / 32;

    // fill stage 0
    {
        int k0 = 0;
        uint32_t st = 0;
        cpa16(d00 + st + 0 * ARRB, g0 + (size_t)r0 * lda + k0 + q0 * 8);
        cpa16(d01 + st + 0 * ARRB, g0 + (size_t)r1 * lda + k0 + q1 * 8);
        cpa16(d00 + st + 1 * ARRB, g1 + (size_t)r0 * lda + k0 + q0 * 8);
        cpa16(d01 + st + 1 * ARRB, g1 + (size_t)r1 * lda + k0 + q1 * 8);
        cpa16(d00 + st + 2 * ARRB, g2 + (size_t)r0 * ldb + k0 + q0 * 8);
        cpa16(d01 + st + 2 * ARRB, g2 + (size_t)r1 * ldb + k0 + q1 * 8);
        cpa16(d00 + st + 3 * ARRB, g3 + (size_t)r0 * ldb + k0 + q0 * 8);
        cpa16(d01 + st + 3 * ARRB, g3 + (size_t)r1 * ldb + k0 + q1 * 8);
        CP_COMMIT();
    }

    uint32_t a_base = sb + (warpM * 64 + (lane & 15)) * SROW + ((lane >> 4) * 16);
    uint32_t b_base = sb + 2 * ARRB + (warpN * 32 + (lane & 7)) * SROW + (((lane >> 3) & 1) * 16);

    for (int it = 0; it < nit; it++) {
        bool pf = (it + 1) < nit;
        if (pf) {
            int k0 = (it + 1) * 32;
            uint32_t st = ((it + 1) & 1) * STAGEB;
            cpa16(d00 + st + 0 * ARRB, g0 + (size_t)r0 * lda + k0 + q0 * 8);
            cpa16(d01 + st + 0 * ARRB, g0 + (size_t)r1 * lda + k0 + q1 * 8);
            cpa16(d00 + st + 1 * ARRB, g1 + (size_t)r0 * lda + k0 + q0 * 8);
            cpa16(d01 + st + 1 * ARRB, g1 + (size_t)r1 * lda + k0 + q1 * 8);
            cpa16(d00 + st + 2 * ARRB, g2 + (size_t)r0 * ldb + k0 + q0 * 8);
            cpa16(d01 + st + 2 * ARRB, g2 + (size_t)r1 * ldb + k0 + q1 * 8);
            cpa16(d00 + st + 3 * ARRB, g3 + (size_t)r0 * ldb + k0 + q0 * 8);
            cpa16(d01 + st + 3 * ARRB, g3 + (size_t)r1 * ldb + k0 + q1 * 8);
            CP_COMMIT();
            CP_WAIT(1);
        } else {
            CP_WAIT(0);
        }
        __syncthreads();

        uint32_t st = (it & 1) * STAGEB;
        uint32_t ab = a_base + st;
        uint32_t bb = b_base + st;
#pragma unroll
        for (int kk = 0; kk < 2; kk++) {
            int kb = kk * 32;   // byte offset within row (16 bf16)
            uint32_t ah[4][4], al[4][4];
#pragma unroll
            for (int mi = 0; mi < 4; mi++) {
                ldsm_x4(ab + mi * (16 * SROW) + kb, ah[mi]);
                ldsm_x4(ab + ARRB + mi * (16 * SROW) + kb, al[mi]);
            }
#pragma unroll
            for (int ni = 0; ni < 4; ni++) {
                uint32_t bh[2], bl[2];
                ldsm_x2(bb + ni * (8 * SROW) + kb, bh);
                ldsm_x2(bb + ARRB + ni * (8 * SROW) + kb, bl);
#pragma unroll
                for (int mi = 0; mi < 4; mi++) {
                    mma_bf16(acc[mi][ni], ah[mi], bh);
                    mma_bf16(acc[mi][ni], ah[mi], bl);
                    mma_bf16(acc[mi][ni], al[mi], bh);
                }
            }
        }
        __syncthreads();
    }

    // ---------------- epilogue ----------------
    int rbase = m0 + warpM * 64 + (lane >> 2);
    int cbase = n0 + warpN * 32 + (lane & 3) * 2;
#pragma unroll
    for (int mi = 0; mi < 4; mi++) {
#pragma unroll
        for (int ni = 0; ni < 4; ni++) {
            int col = cbase + ni * 8;
#pragma unroll
            for (int hf = 0; hf < 2; hf++) {
                int row = rbase + mi * 16 + hf * 8;
                float v0 = acc[mi][ni][hf * 2 + 0];
                float v1 = acc[mi][ni][hf * 2 + 1];
                if (EPI == 0) {
                    float2 o; o.x = alpha * v0; o.y = alpha * v1;
                    *(float2*)&C[(size_t)row * ldc + col] = o;
                } else if (EPI == 2) {
                    float2 o;
                    o.x = res[(size_t)row * ldres + col + 0] + gate[col + 0] * (v0 + bias[col + 0]);
                    o.y = res[(size_t)row * ldres + col + 1] + gate[col + 1] * (v1 + bias[col + 1]);
                    *(float2*)&C[(size_t)row * ldc + col] = o;
                } else { // EPI 3
                    float gg0 = gelu_tanh(v0 + bias[col]);
                    float gg1 = gelu_tanh(v1 + bias[col + 1]);
                    __nv_bfloat16 h0, l0, h1, l1;
                    split2(gg0, h0, l0); split2(gg1, h1, l1);
                    __nv_bfloat162 hp; hp.x = h0; hp.y = h1;
                    __nv_bfloat162 lp; lp.x = l0; lp.y = l1;
                    *(__nv_bfloat162*)&Chi[(size_t)row * ldc + col] = hp;
                    *(__nv_bfloat162*)&Clo[(size_t)row * ldc + col] = lp;
                }
            }
        }
    }
}

// ================= host side =================
#define SYMF(p, s) do { void* _t = nullptr; cudaGetSymbolAddress(&_t, s); (p) = (float*)_t; } while (0)
#define SYMB(p, s) do { void* _t = nullptr; cudaGetSymbolAddress(&_t, s); (p) = (__nv_bfloat16*)_t; } while (0)

extern "C" void kernel_launch(void* const* d_in, const int* in_sizes, int n_in,
                              void* d_out, int out_size) {
    const float* img     = (const float*)d_in[0];
    const float* txt     = (const float*)d_in[1];
    const float* vec     = (const float*)d_in[2];
    const float* pe      = (const float*)d_in[3];
    const float* i_mod_w = (const float*)d_in[4];
    const float* i_mod_b = (const float*)d_in[5];
    const float* i_qkv_w = (const float*)d_in[6];
    const float* i_q_s   = (const float*)d_in[7];
    const float* i_k_s   = (const float*)d_in[8];
    const float* i_pw    = (const float*)d_in[9];
    const float* i_pb    = (const float*)d_in[10];
    const float* i_w1    = (const float*)d_in[11];
    const float* i_b1    = (const float*)d_in[12];
    const float* i_w2    = (const float*)d_in[13];
    const float* i_b2    = (const float*)d_in[14];
    const float* t_mod_w = (const float*)d_in[15];
    const float* t_mod_b = (const float*)d_in[16];
    const float* t_qkv_w = (const float*)d_in[17];
    const float* t_q_s   = (const float*)d_in[18];
    const float* t_k_s   = (const float*)d_in[19];
    const float* t_pw    = (const float*)d_in[20];
    const float* t_pb    = (const float*)d_in[21];
    const float* t_w1    = (const float*)d_in[22];
    const float* t_b1    = (const float*)d_in[23];
    const float* t_w2    = (const float*)d_in[24];
    const float* t_b2    = (const float*)d_in[25];

    float* out_img = (float*)d_out;
    float* out_txt = out_img + (size_t)Li * DD;

    float *sv, *mod_i, *mod_t, *qkv_i, *qkv_t, *scoresb, *ao, *res_i, *res_t;
    __nv_bfloat16 *mxi_h, *mxi_l, *mxt_h, *mxt_l, *wt_h, *wt_l;
    __nv_bfloat16 *qh, *ql, *kh, *kl, *vth, *vtl, *pph, *ppl, *aoh, *aol, *hh, *hl, *mh, *ml;
    SYMF(sv, g_sv); SYMF(mod_i, g_mod_img); SYMF(mod_t, g_mod_txt);
    SYMF(qkv_i, g_qkv_img); SYMF(qkv_t, g_qkv_txt);
    SYMF(scoresb, g_scores); SYMF(ao, g_ao); SYMF(res_i, g_res_i); SYMF(res_t, g_res_t);
    SYMB(mxi_h, g_mxi_h); SYMB(mxi_l, g_mxi_l); SYMB(mxt_h, g_mxt_h); SYMB(mxt_l, g_mxt_l);
    SYMB(wt_h, g_wt_h); SYMB(wt_l, g_wt_l);
    SYMB(qh, g_qh); SYMB(ql, g_ql); SYMB(kh, g_kh); SYMB(kl, g_kl);
    SYMB(vth, g_vth); SYMB(vtl, g_vtl);
    SYMB(pph, g_ph); SYMB(ppl, g_pl);
    SYMB(aoh, g_aoh); SYMB(aol, g_aol);
    SYMB(hh, g_hh); SYMB(hl, g_hl); SYMB(mh, g_mh); SYMB(ml, g_ml);

    cudaFuncSetAttribute(tgemm<0>, cudaFuncAttributeMaxDynamicSharedMemorySize, TGEMM_SMEM);
    cudaFuncSetAttribute(tgemm<2>, cudaFuncAttributeMaxDynamicSharedMemorySize, TGEMM_SMEM);
    cudaFuncSetAttribute(tgemm<3>, cudaFuncAttributeMaxDynamicSharedMemorySize, TGEMM_SMEM);

    dim3 wcb(32, 8);

    // 1. modulation
    silu_k<<<(DD + 255) / 256, 256>>>(vec, sv);
    modmul_k<<<6 * DD / 128, 128>>>(sv, i_mod_w, i_mod_b, mod_i);
    modmul_k<<<6 * DD / 128, 128>>>(sv, t_mod_w, t_mod_b, mod_t);

    // 2. LN1 + modulate -> bf16 hi/lo
    ln_mod_split_k<<<Li, 256>>>(img, mxi_h, mxi_l, mod_i + 0 * DD, mod_i + 1 * DD);
    ln_mod_split_k<<<Lt, 256>>>(txt, mxt_h, mxt_l, mod_t + 0 * DD, mod_t + 1 * DD);

    // 3. QKV GEMMs
    wconv_k<<<dim3(3 * DD / 32, DD / 32), wcb>>>(i_qkv_w, wt_h, wt_l, DD, 3 * DD);
    tgemm<0><<<dim3(3 * DD / 128, Li / 128, 1), 256, TGEMM_SMEM>>>(
        mxi_h, mxi_l, 0, wt_h, wt_l, 0, qkv_i, 0, nullptr, nullptr,
        DD, DD, DD, 3 * DD, 1.0f, nullptr, nullptr, nullptr, 0);
    wconv_k<<<dim3(3 * DD / 32, DD / 32), wcb>>>(t_qkv_w, wt_h, wt_l, DD, 3 * DD);
    tgemm<0><<<dim3(3 * DD / 128, Lt / 128, 1), 256, TGEMM_SMEM>>>(
        mxt_h, mxt_l, 0, wt_h, wt_l, 0, qkv_t, 0, nullptr, nullptr,
        DD, DD, DD, 3 * DD, 1.0f, nullptr, nullptr, nullptr, 0);

    // 4. split + rmsnorm + rope -> bf16 hi/lo
    qkv_prep_k<<<dim3(HH, LL), HD>>>(qkv_t, qkv_i, t_q_s, t_k_s, i_q_s, i_k_s, pe,
                                     qh, ql, kh, kl, vth, vtl);

    // 5. attention (batched over heads)
    const float iscale = 0.08838834764831845f; // 1/sqrt(128)
    tgemm<0><<<dim3(LL / 128, LL / 128, HH), 256, TGEMM_SMEM>>>(
        qh, ql, (long long)LL * HD, kh, kl, (long long)LL * HD,
        scoresb, (long long)LL * LL, nullptr, nullptr,
        HD, HD, HD, LL, iscale, nullptr, nullptr, nullptr, 0);
    softmax_split_k<<<HH * LL, 256>>>(scoresb, pph, ppl, LL);
    tgemm<0><<<dim3(1, LL / 128, HH), 256, TGEMM_SMEM>>>(
        pph, ppl, (long long)LL * LL, vth, vtl, (long long)HD * LL,
        ao, (long long)HD, nullptr, nullptr,
        LL, LL, LL, DD, 1.0f, nullptr, nullptr, nullptr, 0);

    // 6. proj + gated residual
    split_k<<<((size_t)LL * DD + 255) / 256, 256>>>(ao, aoh, aol, (size_t)LL * DD);
    wconv_k<<<dim3(DD / 32, DD / 32), wcb>>>(i_pw, wt_h, wt_l, DD, DD);
    tgemm<2><<<dim3(DD / 128, Li / 128, 1), 256, TGEMM_SMEM>>>(
        aoh + (size_t)Lt * DD, aol + (size_t)Lt * DD, 0, wt_h, wt_l, 0,
        res_i, 0, nullptr, nullptr,
        DD, DD, DD, DD, 1.0f, i_pb, mod_i + 2 * DD, img, DD);
    wconv_k<<<dim3(DD / 32, DD / 32), wcb>>>(t_pw, wt_h, wt_l, DD, DD);
    tgemm<2><<<dim3(DD / 128, Lt / 128, 1), 256, TGEMM_SMEM>>>(
        aoh, aol, 0, wt_h, wt_l, 0, res_t, 0, nullptr, nullptr,
        DD, DD, DD, DD, 1.0f, t_pb, mod_t + 2 * DD, txt, DD);

    // 7. img MLP
    ln_mod_split_k<<<Li, 256>>>(res_i, hh, hl, mod_i + 3 * DD, mod_i + 4 * DD);
    wconv_k<<<dim3(MLPD / 32, DD / 32), wcb>>>(i_w1, wt_h, wt_l, DD, MLPD);
    tgemm<3><<<dim3(MLPD / 128, Li / 128, 1), 256, TGEMM_SMEM>>>(
        hh, hl, 0, wt_h, wt_l, 0, nullptr, 0, mh, ml,
        DD, DD, DD, MLPD, 1.0f, i_b1, nullptr, nullptr, 0);
    wconv_k<<<dim3(DD / 32, MLPD / 32), wcb>>>(i_w2, wt_h, wt_l, MLPD, DD);
    tgemm<2><<<dim3(DD / 128, Li / 128, 1), 256, TGEMM_SMEM>>>(
        mh, ml, 0, wt_h, wt_l, 0, out_img, 0, nullptr, nullptr,
        MLPD, MLPD, MLPD, DD, 1.0f, i_b2, mod_i + 5 * DD, res_i, DD);

    // 8. txt MLP
    ln_mod_split_k<<<Lt, 256>>>(res_t, hh, hl, mod_t + 3 * DD, mod_t + 4 * DD);
    wconv_k<<<dim3(MLPD / 32, DD / 32), wcb>>>(t_w1, wt_h, wt_l, DD, MLPD);
    tgemm<3><<<dim3(MLPD / 128, Lt / 128, 1), 256, TGEMM_SMEM>>>(
        hh, hl, 0, wt_h, wt_l, 0, nullptr, 0, mh, ml,
        DD, DD, DD, MLPD, 1.0f, t_b1, nullptr, nullptr, 0);
    wconv_k<<<dim3(DD / 32, MLPD / 32), wcb>>>(t_w2, wt_h, wt_l, MLPD, DD);
    tgemm<2><<<dim3(DD / 128, Lt / 128, 1), 256, TGEMM_SMEM>>>(
        mh, ml, 0, wt_h, wt_l, 0, out_txt, 0, nullptr, nullptr,
        MLPD, MLPD, MLPD, DD, 1.0f, t_b2, mod_t + 5 * DD, res_t, DD);

    (void)in_sizes; (void)n_in; (void)out_size;
}

// round 6
// speedup vs baseline: 4.2546x; 1.0957x over previous
#include <cuda_runtime.h>
#include <cuda_fp16.h>
#include <math.h>
#include <stdint.h>

#define Lt 256
#define Li 2048
#define LL 2304          // Lt + Li
#define DD 2048
#define HH 16
#define HD 128
#define MLPD 8192
#define EPSF 1e-6f

// ================= helpers =================
__device__ __forceinline__ uint32_t smem_to_u32(const void* p) {
    uint32_t a;
    asm("{ .reg .u64 t; cvta.to.shared.u64 t, %1; cvt.u32.u64 %0, t; }" : "=r"(a) : "l"(p));
    return a;
}
__device__ __forceinline__ void cpa16(uint32_t dst, const void* src) {
    asm volatile("cp.async.cg.shared.global [%0], [%1], 16;" :: "r"(dst), "l"(src));
}
#define CP_COMMIT() asm volatile("cp.async.commit_group;" ::: "memory")
#define CP_WAIT(N)  asm volatile("cp.async.wait_group %0;" :: "n"(N) : "memory")

__device__ __forceinline__ void ldsm_x4(uint32_t addr, uint32_t* r) {
    asm volatile("ldmatrix.sync.aligned.m8n8.x4.shared.b16 {%0,%1,%2,%3}, [%4];"
                 : "=r"(r[0]), "=r"(r[1]), "=r"(r[2]), "=r"(r[3]) : "r"(addr));
}
__device__ __forceinline__ void ldsm_x2(uint32_t addr, uint32_t* r) {
    asm volatile("ldmatrix.sync.aligned.m8n8.x2.shared.b16 {%0,%1}, [%2];"
                 : "=r"(r[0]), "=r"(r[1]) : "r"(addr));
}
__device__ __forceinline__ void mma_fp16(float* d, const uint32_t* a, const uint32_t* b) {
    asm volatile(
        "mma.sync.aligned.m16n8k16.row.col.f32.f16.f16.f32 "
        "{%0,%1,%2,%3}, {%4,%5,%6,%7}, {%8,%9}, {%0,%1,%2,%3};"
        : "+f"(d[0]), "+f"(d[1]), "+f"(d[2]), "+f"(d[3])
        : "r"(a[0]), "r"(a[1]), "r"(a[2]), "r"(a[3]), "r"(b[0]), "r"(b[1]));
}

__device__ __forceinline__ void split2(float x, __half& h, __half& l) {
    h = __float2half_rn(x);
    l = __float2half_rn(x - __half2float(h));
}
__device__ __forceinline__ uint32_t packh2(float a, float b) {
    __half2 t = __floats2half2_rn(a, b);
    return *(uint32_t*)&t;
}
__device__ __forceinline__ float gelu_tanh(float x) {
    float x3 = x * x * x;
    return 0.5f * x * (1.0f + tanhf(0.7978845608028654f * (x + 0.044715f * x3)));
}

// ================= scratch (static device globals) =================
__device__ __align__(16) float g_sv[DD];
__device__ __align__(16) float g_mod_img[6 * DD];
__device__ __align__(16) float g_mod_txt[6 * DD];
__device__ __align__(16) __half g_mxi_h[Li * DD];
__device__ __align__(16) __half g_mxi_l[Li * DD];
__device__ __align__(16) __half g_mxt_h[Lt * DD];
__device__ __align__(16) __half g_mxt_l[Lt * DD];
__device__ __align__(16) __half g_wt_h[MLPD * DD];
__device__ __align__(16) __half g_wt_l[MLPD * DD];
__device__ __align__(16) float g_qkv_img[Li * 3 * DD];
__device__ __align__(16) float g_qkv_txt[Lt * 3 * DD];
__device__ __align__(16) __half g_qh[HH * LL * HD];
__device__ __align__(16) __half g_ql[HH * LL * HD];
__device__ __align__(16) __half g_kh[HH * LL * HD];
__device__ __align__(16) __half g_kl[HH * LL * HD];
__device__ __align__(16) __half g_vth[HH * HD * LL]; // V transposed per head [H, HD, LL]
__device__ __align__(16) __half g_vtl[HH * HD * LL];
__device__ __align__(16) __half g_aoh[LL * DD];
__device__ __align__(16) __half g_aol[LL * DD];
__device__ __align__(16) float g_res_i[Li * DD];
__device__ __align__(16) float g_res_t[Lt * DD];
__device__ __align__(16) __half g_hh[Li * DD];
__device__ __align__(16) __half g_hl[Li * DD];
__device__ __align__(16) __half g_mh[(size_t)Li * MLPD];
__device__ __align__(16) __half g_ml[(size_t)Li * MLPD];

// ================= small kernels =================
__global__ void silu_k(const float* __restrict__ vec, float* __restrict__ sv) {
    int i = blockIdx.x * blockDim.x + threadIdx.x;
    if (i < DD) { float x = vec[i]; sv[i] = x / (1.0f + __expf(-x)); }
}

__global__ void modmul_k(const float* __restrict__ sv, const float* __restrict__ W,
                         const float* __restrict__ b, float* __restrict__ out) {
    __shared__ float s[DD];
    for (int i = threadIdx.x; i < DD; i += 128) s[i] = sv[i];
    __syncthreads();
    int j = blockIdx.x * 128 + threadIdx.x;
    float acc = 0.0f;
    const float* wp = W + j;
    for (int d = 0; d < DD; d++) acc += s[d] * wp[(size_t)d * (6 * DD)];
    out[j] = acc + b[j];
}

// y_hi/y_lo = split((1+sc)*LN(x) + sh)
__global__ void ln_mod_split_k(const float* __restrict__ x,
                               __half* __restrict__ yh, __half* __restrict__ yl,
                               const float* __restrict__ sh, const float* __restrict__ sc) {
    int row = blockIdx.x;
    const float* px = x + (size_t)row * DD;
    __shared__ float red[256];
    int tid = threadIdx.x;
    float v[8];
    float s = 0.0f;
#pragma unroll
    for (int i = 0; i < 8; i++) { v[i] = px[tid + i * 256]; s += v[i]; }
    red[tid] = s; __syncthreads();
    for (int o = 128; o > 0; o >>= 1) { if (tid < o) red[tid] += red[tid + o]; __syncthreads(); }
    float mu = red[0] * (1.0f / DD);
    __syncthreads();
    float ss = 0.0f;
#pragma unroll
    for (int i = 0; i < 8; i++) { float d = v[i] - mu; ss += d * d; }
    red[tid] = ss; __syncthreads();
    for (int o = 128; o > 0; o >>= 1) { if (tid < o) red[tid] += red[tid + o]; __syncthreads(); }
    float r = rsqrtf(red[0] * (1.0f / DD) + EPSF);
#pragma unroll
    for (int i = 0; i < 8; i++) {
        int c = tid + i * 256;
        float y = (1.0f + sc[c]) * ((v[i] - mu) * r) + sh[c];
        __half h, l; split2(y, h, l);
        yh[(size_t)row * DD + c] = h;
        yl[(size_t)row * DD + c] = l;
    }
}

// transpose + split: W[K,N] fp32 -> Wt_hi/lo [N,K] fp16
__global__ void wconv_k(const float* __restrict__ W,
                        __half* __restrict__ Wh, __half* __restrict__ Wl,
                        int Kd, int Nd) {
    __shared__ float t[32][33];
    int n = blockIdx.x * 32 + threadIdx.x;
#pragma unroll
    for (int i = 0; i < 4; i++) {
        int k = blockIdx.y * 32 + threadIdx.y + i * 8;
        t[threadIdx.y + i * 8][threadIdx.x] = W[(size_t)k * Nd + n];
    }
    __syncthreads();
    int k2 = blockIdx.y * 32 + threadIdx.x;
#pragma unroll
    for (int i = 0; i < 4; i++) {
        int n2 = blockIdx.x * 32 + threadIdx.y + i * 8;
        float v = t[threadIdx.x][threadIdx.y + i * 8];
        __half h, l; split2(v, h, l);
        Wh[(size_t)n2 * Kd + k2] = h;
        Wl[(size_t)n2 * Kd + k2] = l;
    }
}

// split qkv, rmsnorm(q,k)*scale, rope(q,k) -> hi/lo fp16 (q,k [H,L,HD]; v transposed [H,HD,L])
__global__ void qkv_prep_k(const float* __restrict__ qkv_txt, const float* __restrict__ qkv_img,
                           const float* __restrict__ tq_s, const float* __restrict__ tk_s,
                           const float* __restrict__ iq_s, const float* __restrict__ ik_s,
                           const float* __restrict__ pe,
                           __half* __restrict__ qh, __half* __restrict__ ql,
                           __half* __restrict__ kh, __half* __restrict__ kl,
                           __half* __restrict__ vth, __half* __restrict__ vtl) {
    int h = blockIdx.x;
    int pos = blockIdx.y;
    int d = threadIdx.x;
    const float* src; int l; const float* qs; const float* ks;
    if (pos < Lt) { src = qkv_txt; l = pos;      qs = tq_s; ks = tk_s; }
    else          { src = qkv_img; l = pos - Lt; qs = iq_s; ks = ik_s; }
    const float* base = src + (size_t)l * (3 * DD) + h * HD;
    float qv = base[d];
    float kv = base[DD + d];
    float vv = base[2 * DD + d];

    __shared__ float sq[HD], sk[HD], red[8];
    float q2 = qv * qv, k2 = kv * kv;
#pragma unroll
    for (int o = 16; o > 0; o >>= 1) {
        q2 += __shfl_xor_sync(0xFFFFFFFFu, q2, o);
        k2 += __shfl_xor_sync(0xFFFFFFFFu, k2, o);
    }
    int w = d >> 5;
    if ((d & 31) == 0) { red[w] = q2; red[4 + w] = k2; }
    __syncthreads();
    float qss = red[0] + red[1] + red[2] + red[3];
    float kss = red[4] + red[5] + red[6] + red[7];
    float qn = qv * rsqrtf(qss * (1.0f / HD) + EPSF) * qs[d];
    float kn = kv * rsqrtf(kss * (1.0f / HD) + EPSF) * ks[d];
    sq[d] = qn; sk[d] = kn;
    __syncthreads();
    int i = d >> 1, j = d & 1;
    const float* pp = pe + (((size_t)pos * 64 + i) * 4 + j * 2);
    float p0 = pp[0], p1 = pp[1];
    float rq = p0 * sq[2 * i] + p1 * sq[2 * i + 1];
    float rk = p0 * sk[2 * i] + p1 * sk[2 * i + 1];
    size_t o = ((size_t)h * LL + pos) * HD + d;
    __half a, b;
    split2(rq, a, b); qh[o] = a; ql[o] = b;
    split2(rk, a, b); kh[o] = a; kl[o] = b;
    size_t ov = ((size_t)h * HD + d) * LL + pos;
    split2(vv, a, b); vth[ov] = a; vtl[ov] = b;
}

// ================= fused flash attention =================
// Per CTA: one head, 128 Q rows. KV chunks of 64, double-buffered cp.async.
// 8 warps, each owns 16 Q rows. S/P + online softmax + O accumulation in registers.
// Output: normalized O written directly as hi/lo fp16 into aoh/aol [LL, DD].
#define FCHUNK 64
#define NCHUNK (LL / FCHUNK)       // 36
#define F_QROW 272                 // 128 cols fp16 + 16B pad
#define F_QSZ  (128 * F_QROW)      // 34816 per array
#define F_KROW 272
#define F_KSZ  (64 * F_KROW)       // 17408 per array
#define F_VROW 144                 // 64 cols fp16 + 16B pad
#define F_VSZ  (128 * F_VROW)      // 18432 per array
#define F_STG0 (2 * F_QSZ)         // 69632
#define F_STGSZ (2 * F_KSZ + 2 * F_VSZ)  // 71680
#define FLASH_SMEM (F_STG0 + 2 * F_STGSZ) // 212992

__global__ __launch_bounds__(256, 1) void flash_k(
    const __half* __restrict__ qhg, const __half* __restrict__ qlg,
    const __half* __restrict__ khg, const __half* __restrict__ klg,
    const __half* __restrict__ vthg, const __half* __restrict__ vtlg,
    __half* __restrict__ aoh, __half* __restrict__ aol) {
    extern __shared__ char smem[];
    uint32_t sb = smem_to_u32(smem);
    int tid = threadIdx.x, wid = tid >> 5, lane = tid & 31;
    int h = blockIdx.y, qt = blockIdx.x;
    const float iscale = 0.08838834764831845f; // 1/sqrt(128)

    // ---- load Q tile (once) ----
#pragma unroll
    for (int i = 0; i < 8; i++) {
        int u = tid + i * 256;          // 0..2047
        int row = u >> 4, cu = u & 15;
        size_t go = ((size_t)h * LL + qt * 128 + row) * HD + cu * 8;
        cpa16(sb + row * F_QROW + cu * 16, qhg + go);
        cpa16(sb + F_QSZ + row * F_QROW + cu * 16, qlg + go);
    }
    CP_COMMIT();

    // ---- prefetch chunk 0 ----
    {
        uint32_t st = sb + F_STG0;
#pragma unroll
        for (int i = 0; i < 4; i++) {
            int u = tid + i * 256;      // 0..1023
            int row = u >> 4, cu = u & 15;
            size_t go = ((size_t)h * LL + row) * HD + cu * 8;
            cpa16(st + row * F_KROW + cu * 16, khg + go);
            cpa16(st + F_KSZ + row * F_KROW + cu * 16, klg + go);
            int vr = u >> 3, vc = u & 7;
            size_t gv = ((size_t)h * HD + vr) * LL + vc * 8;
            cpa16(st + 2 * F_KSZ + vr * F_VROW + vc * 16, vthg + gv);
            cpa16(st + 2 * F_KSZ + F_VSZ + vr * F_VROW + vc * 16, vtlg + gv);
        }
        CP_COMMIT();
    }

    float o[16][4];
#pragma unroll
    for (int i = 0; i < 16; i++)
#pragma unroll
        for (int f = 0; f < 4; f++) o[i][f] = 0.0f;
    float m0 = -1e30f, m1 = -1e30f, l0 = 0.0f, l1 = 0.0f;

    uint32_t qa_base = sb + (wid * 16 + (lane & 15)) * F_QROW + ((lane >> 4) * 16);

    for (int j = 0; j < NCHUNK; j++) {
        CP_WAIT(0);
        __syncthreads();
        // prefetch next chunk into the other stage
        if (j + 1 < NCHUNK) {
            int ln = (j + 1) * FCHUNK;
            uint32_t st = sb + F_STG0 + ((j + 1) & 1) * F_STGSZ;
#pragma unroll
            for (int i = 0; i < 4; i++) {
                int u = tid + i * 256;
                int row = u >> 4, cu = u & 15;
                size_t go = ((size_t)h * LL + ln + row) * HD + cu * 8;
                cpa16(st + row * F_KROW + cu * 16, khg + go);
                cpa16(st + F_KSZ + row * F_KROW + cu * 16, klg + go);
                int vr = u >> 3, vc = u & 7;
                size_t gv = ((size_t)h * HD + vr) * LL + ln + vc * 8;
                cpa16(st + 2 * F_KSZ + vr * F_VROW + vc * 16, vthg + gv);
                cpa16(st + 2 * F_KSZ + F_VSZ + vr * F_VROW + vc * 16, vtlg + gv);
            }
            CP_COMMIT();
        }

        uint32_t st = sb + F_STG0 + (j & 1) * F_STGSZ;

        // ---- S = Q @ K^T (m16 x n64 per warp) ----
        float S[8][4];
#pragma unroll
        for (int i = 0; i < 8; i++)
#pragma unroll
            for (int f = 0; f < 4; f++) S[i][f] = 0.0f;
#pragma unroll
        for (int kk = 0; kk < 8; kk++) {
            uint32_t aH[4], aL[4];
            uint32_t qa = qa_base + kk * 32;
            ldsm_x4(qa, aH);
            ldsm_x4(qa + F_QSZ, aL);
#pragma unroll
            for (int ni = 0; ni < 8; ni++) {
                uint32_t bH[2], bL[2];
                uint32_t ka = st + (ni * 8 + (lane & 7)) * F_KROW + ((lane >> 3) & 1) * 16 + kk * 32;
                ldsm_x2(ka, bH);
                ldsm_x2(ka + F_KSZ, bL);
                mma_fp16(S[ni], aH, bH);
                mma_fp16(S[ni], aH, bL);
                mma_fp16(S[ni], aL, bH);
            }
        }

        // ---- online softmax ----
        float rm0 = -1e30f, rm1 = -1e30f;
#pragma unroll
        for (int ni = 0; ni < 8; ni++) {
            rm0 = fmaxf(rm0, fmaxf(S[ni][0], S[ni][1]));
            rm1 = fmaxf(rm1, fmaxf(S[ni][2], S[ni][3]));
        }
        rm0 = fmaxf(rm0, __shfl_xor_sync(0xFFFFFFFFu, rm0, 1));
        rm0 = fmaxf(rm0, __shfl_xor_sync(0xFFFFFFFFu, rm0, 2));
        rm1 = fmaxf(rm1, __shfl_xor_sync(0xFFFFFFFFu, rm1, 1));
        rm1 = fmaxf(rm1, __shfl_xor_sync(0xFFFFFFFFu, rm1, 2));
        float mn0 = fmaxf(m0, rm0), mn1 = fmaxf(m1, rm1);
        float f0 = __expf((m0 - mn0) * iscale);
        float f1 = __expf((m1 - mn1) * iscale);
        m0 = mn0; m1 = mn1;
        float rs0 = 0.0f, rs1 = 0.0f;
#pragma unroll
        for (int ni = 0; ni < 8; ni++) {
            S[ni][0] = __expf((S[ni][0] - mn0) * iscale);
            S[ni][1] = __expf((S[ni][1] - mn0) * iscale);
            S[ni][2] = __expf((S[ni][2] - mn1) * iscale);
            S[ni][3] = __expf((S[ni][3] - mn1) * iscale);
            rs0 += S[ni][0] + S[ni][1];
            rs1 += S[ni][2] + S[ni][3];
        }
        rs0 += __shfl_xor_sync(0xFFFFFFFFu, rs0, 1);
        rs0 += __shfl_xor_sync(0xFFFFFFFFu, rs0, 2);
        rs1 += __shfl_xor_sync(0xFFFFFFFFu, rs1, 1);
        rs1 += __shfl_xor_sync(0xFFFFFFFFu, rs1, 2);
        l0 = l0 * f0 + rs0;
        l1 = l1 * f1 + rs1;
#pragma unroll
        for (int ni = 0; ni < 16; ni++) {
            o[ni][0] *= f0; o[ni][1] *= f0;
            o[ni][2] *= f1; o[ni][3] *= f1;
        }

        // ---- O += P @ V ----
#pragma unroll
        for (int kf = 0; kf < 4; kf++) {
            uint32_t pH[4], pL[4];
            {
                float* c0 = S[2 * kf];
                float* c1 = S[2 * kf + 1];
                __half2 t;
                t = __floats2half2_rn(c0[0], c0[1]); pH[0] = *(uint32_t*)&t;
                float r00 = c0[0] - __low2float(t), r01 = c0[1] - __high2float(t);
                t = __floats2half2_rn(c0[2], c0[3]); pH[1] = *(uint32_t*)&t;
                float r02 = c0[2] - __low2float(t), r03 = c0[3] - __high2float(t);
                t = __floats2half2_rn(c1[0], c1[1]); pH[2] = *(uint32_t*)&t;
                float r10 = c1[0] - __low2float(t), r11 = c1[1] - __high2float(t);
                t = __floats2half2_rn(c1[2], c1[3]); pH[3] = *(uint32_t*)&t;
                float r12 = c1[2] - __low2float(t), r13 = c1[3] - __high2float(t);
                pL[0] = packh2(r00, r01); pL[1] = packh2(r02, r03);
                pL[2] = packh2(r10, r11); pL[3] = packh2(r12, r13);
            }
#pragma unroll
            for (int ni = 0; ni < 16; ni++) {
                uint32_t bH[2], bL[2];
                uint32_t va = st + 2 * F_KSZ + (ni * 8 + (lane & 7)) * F_VROW +
                              ((lane >> 3) & 1) * 16 + kf * 32;
                ldsm_x2(va, bH);
                ldsm_x2(va + F_VSZ, bL);
                mma_fp16(o[ni], pH, bH);
                mma_fp16(o[ni], pH, bL);
                mma_fp16(o[ni], pL, bH);
            }
        }
        __syncthreads();
    }

    // ---- normalize + write out split hi/lo ----
    float inv0 = 1.0f / l0, inv1 = 1.0f / l1;
    int row0 = qt * 128 + wid * 16 + (lane >> 2);
    int row1 = row0 + 8;
#pragma unroll
    for (int ni = 0; ni < 16; ni++) {
        int col = h * HD + ni * 8 + (lane & 3) * 2;
        float a0 = o[ni][0] * inv0, a1 = o[ni][1] * inv0;
        float b0 = o[ni][2] * inv1, b1 = o[ni][3] * inv1;
        __half2 h0 = __floats2half2_rn(a0, a1);
        __half2 l0v; { float x = a0 - __low2float(h0), y = a1 - __high2float(h0); l0v = __floats2half2_rn(x, y); }
        __half2 h1 = __floats2half2_rn(b0, b1);
        __half2 l1v; { float x = b0 - __low2float(h1), y = b1 - __high2float(h1); l1v = __floats2half2_rn(x, y); }
        *(__half2*)&aoh[(size_t)row0 * DD + col] = h0;
        *(__half2*)&aol[(size_t)row0 * DD + col] = l0v;
        *(__half2*)&aoh[(size_t)row1 * DD + col] = h1;
        *(__half2*)&aol[(size_t)row1 * DD + col] = l1v;
    }
}

// ================= HMMA (mma.sync fp16) GEMM =================
// C[M,N] = epi( (Ah+Al)[M,K] @ (Bh+Bl)[N,K]^T ), 3-product hi/lo split, fp32 accum.
// CTA tile 128x128, BK=32. 8 warps (2x4), warp tile 64x32.
#define SROW 80
#define ARRB (128 * SROW)
#define STAGEB (4 * ARRB)
#define TGEMM_SMEM (2 * STAGEB)

template <int EPI>
__global__ __launch_bounds__(256, 1) void tgemm(
    const __half* __restrict__ Ah, const __half* __restrict__ Al, long long sAz,
    const __half* __restrict__ Bh, const __half* __restrict__ Bl, long long sBz,
    float* __restrict__ C, long long sCz,
    __half* __restrict__ Chi, __half* __restrict__ Clo,
    int K, int lda, int ldb, int ldc, float alpha,
    const float* __restrict__ bias, const float* __restrict__ gate,
    const float* __restrict__ res, int ldres) {
    extern __shared__ char smem[];
    uint32_t sb = smem_to_u32(smem);
    int tid = threadIdx.x, wid = tid >> 5, lane = tid & 31;
    int warpM = wid >> 2, warpN = wid & 3;
    int m0 = blockIdx.y * 128, n0 = blockIdx.x * 128;
    int z = blockIdx.z;
    Ah += (size_t)z * sAz; Al += (size_t)z * sAz;
    Bh += (size_t)z * sBz; Bl += (size_t)z * sBz;
    if (C)   C   += (size_t)z * sCz;
    if (Chi) { Chi += (size_t)z * sCz; Clo += (size_t)z * sCz; }

    const __half* g0 = Ah + (size_t)m0 * lda;
    const __half* g1 = Al + (size_t)m0 * lda;
    const __half* g2 = Bh + (size_t)n0 * ldb;
    const __half* g3 = Bl + (size_t)n0 * ldb;

    int r0 = tid >> 2, q0 = tid & 3;
    int r1 = (tid + 256) >> 2, q1 = q0;
    uint32_t d00 = sb + r0 * SROW + q0 * 16;
    uint32_t d01 = sb + r1 * SROW + q1 * 16;

    float acc[4][4][4];
#pragma unroll
    for (int i = 0; i < 4; i++)
#pragma unroll
        for (int j = 0; j < 4; j++)
#pragma unroll
            for (int f = 0; f < 4; f++) acc[i][j][f] = 0.0f;

    int nit = K / 32;

    {
        int k0 = 0;
        uint32_t st = 0;
        cpa16(d00 + st + 0 * ARRB, g0 + (size_t)r0 * lda + k0 + q0 * 8);
        cpa16(d01 + st + 0 * ARRB, g0 + (size_t)r1 * lda + k0 + q1 * 8);
        cpa16(d00 + st + 1 * ARRB, g1 + (size_t)r0 * lda + k0 + q0 * 8);
        cpa16(d01 + st + 1 * ARRB, g1 + (size_t)r1 * lda + k0 + q1 * 8);
        cpa16(d00 + st + 2 * ARRB, g2 + (size_t)r0 * ldb + k0 + q0 * 8);
        cpa16(d01 + st + 2 * ARRB, g2 + (size_t)r1 * ldb + k0 + q1 * 8);
        cpa16(d00 + st + 3 * ARRB, g3 + (size_t)r0 * ldb + k0 + q0 * 8);
        cpa16(d01 + st + 3 * ARRB, g3 + (size_t)r1 * ldb + k0 + q1 * 8);
        CP_COMMIT();
    }

    uint32_t a_base = sb + (warpM * 64 + (lane & 15)) * SROW + ((lane >> 4) * 16);
    uint32_t b_base = sb + 2 * ARRB + (warpN * 32 + (lane & 7)) * SROW + (((lane >> 3) & 1) * 16);

    for (int it = 0; it < nit; it++) {
        bool pf = (it + 1) < nit;
        if (pf) {
            int k0 = (it + 1) * 32;
            uint32_t st = ((it + 1) & 1) * STAGEB;
            cpa16(d00 + st + 0 * ARRB, g0 + (size_t)r0 * lda + k0 + q0 * 8);
            cpa16(d01 + st + 0 * ARRB, g0 + (size_t)r1 * lda + k0 + q1 * 8);
            cpa16(d00 + st + 1 * ARRB, g1 + (size_t)r0 * lda + k0 + q0 * 8);
            cpa16(d01 + st + 1 * ARRB, g1 + (size_t)r1 * lda + k0 + q1 * 8);
            cpa16(d00 + st + 2 * ARRB, g2 + (size_t)r0 * ldb + k0 + q0 * 8);
            cpa16(d01 + st + 2 * ARRB, g2 + (size_t)r1 * ldb + k0 + q1 * 8);
            cpa16(d00 + st + 3 * ARRB, g3 + (size_t)r0 * ldb + k0 + q0 * 8);
            cpa16(d01 + st + 3 * ARRB, g3 + (size_t)r1 * ldb + k0 + q1 * 8);
            CP_COMMIT();
            CP_WAIT(1);
        } else {
            CP_WAIT(0);
        }
        __syncthreads();

        uint32_t st = (it & 1) * STAGEB;
        uint32_t ab = a_base + st;
        uint32_t bb = b_base + st;
#pragma unroll
        for (int kk = 0; kk < 2; kk++) {
            int kb = kk * 32;
            uint32_t ah[4][4], al[4][4];
#pragma unroll
            for (int mi = 0; mi < 4; mi++) {
                ldsm_x4(ab + mi * (16 * SROW) + kb, ah[mi]);
                ldsm_x4(ab + ARRB + mi * (16 * SROW) + kb, al[mi]);
            }
#pragma unroll
            for (int ni = 0; ni < 4; ni++) {
                uint32_t bh[2], bl[2];
                ldsm_x2(bb + ni * (8 * SROW) + kb, bh);
                ldsm_x2(bb + ARRB + ni * (8 * SROW) + kb, bl);
#pragma unroll
                for (int mi = 0; mi < 4; mi++) {
                    mma_fp16(acc[mi][ni], ah[mi], bh);
                    mma_fp16(acc[mi][ni], ah[mi], bl);
                    mma_fp16(acc[mi][ni], al[mi], bh);
                }
            }
        }
        __syncthreads();
    }

    int rbase = m0 + warpM * 64 + (lane >> 2);
    int cbase = n0 + warpN * 32 + (lane & 3) * 2;
#pragma unroll
    for (int mi = 0; mi < 4; mi++) {
#pragma unroll
        for (int ni = 0; ni < 4; ni++) {
            int col = cbase + ni * 8;
#pragma unroll
            for (int hf = 0; hf < 2; hf++) {
                int row = rbase + mi * 16 + hf * 8;
                float v0 = acc[mi][ni][hf * 2 + 0];
                float v1 = acc[mi][ni][hf * 2 + 1];
                if (EPI == 0) {
                    float2 oo; oo.x = alpha * v0; oo.y = alpha * v1;
                    *(float2*)&C[(size_t)row * ldc + col] = oo;
                } else if (EPI == 2) {
                    float2 oo;
                    oo.x = res[(size_t)row * ldres + col + 0] + gate[col + 0] * (v0 + bias[col + 0]);
                    oo.y = res[(size_t)row * ldres + col + 1] + gate[col + 1] * (v1 + bias[col + 1]);
                    *(float2*)&C[(size_t)row * ldc + col] = oo;
                } else { // EPI 3
                    float gg0 = gelu_tanh(v0 + bias[col]);
                    float gg1 = gelu_tanh(v1 + bias[col + 1]);
                    __half2 hp = __floats2half2_rn(gg0, gg1);
                    float rr0 = gg0 - __low2float(hp), rr1 = gg1 - __high2float(hp);
                    __half2 lp = __floats2half2_rn(rr0, rr1);
                    *(__half2*)&Chi[(size_t)row * ldc + col] = hp;
                    *(__half2*)&Clo[(size_t)row * ldc + col] = lp;
                }
            }
        }
    }
}

// ================= host side =================
#define SYMF(p, s) do { void* _t = nullptr; cudaGetSymbolAddress(&_t, s); (p) = (float*)_t; } while (0)
#define SYMH(p, s) do { void* _t = nullptr; cudaGetSymbolAddress(&_t, s); (p) = (__half*)_t; } while (0)

extern "C" void kernel_launch(void* const* d_in, const int* in_sizes, int n_in,
                              void* d_out, int out_size) {
    const float* img     = (const float*)d_in[0];
    const float* txt     = (const float*)d_in[1];
    const float* vec     = (const float*)d_in[2];
    const float* pe      = (const float*)d_in[3];
    const float* i_mod_w = (const float*)d_in[4];
    const float* i_mod_b = (const float*)d_in[5];
    const float* i_qkv_w = (const float*)d_in[6];
    const float* i_q_s   = (const float*)d_in[7];
    const float* i_k_s   = (const float*)d_in[8];
    const float* i_pw    = (const float*)d_in[9];
    const float* i_pb    = (const float*)d_in[10];
    const float* i_w1    = (const float*)d_in[11];
    const float* i_b1    = (const float*)d_in[12];
    const float* i_w2    = (const float*)d_in[13];
    const float* i_b2    = (const float*)d_in[14];
    const float* t_mod_w = (const float*)d_in[15];
    const float* t_mod_b = (const float*)d_in[16];
    const float* t_qkv_w = (const float*)d_in[17];
    const float* t_q_s   = (const float*)d_in[18];
    const float* t_k_s   = (const float*)d_in[19];
    const float* t_pw    = (const float*)d_in[20];
    const float* t_pb    = (const float*)d_in[21];
    const float* t_w1    = (const float*)d_in[22];
    const float* t_b1    = (const float*)d_in[23];
    const float* t_w2    = (const float*)d_in[24];
    const float* t_b2    = (const float*)d_in[25];

    float* out_img = (float*)d_out;
    float* out_txt = out_img + (size_t)Li * DD;

    float *sv, *mod_i, *mod_t, *qkv_i, *qkv_t, *res_i, *res_t;
    __half *mxi_h, *mxi_l, *mxt_h, *mxt_l, *wt_h, *wt_l;
    __half *qh, *ql, *kh, *kl, *vth, *vtl, *aoh, *aol, *hh, *hl, *mh, *ml;
    SYMF(sv, g_sv); SYMF(mod_i, g_mod_img); SYMF(mod_t, g_mod_txt);
    SYMF(qkv_i, g_qkv_img); SYMF(qkv_t, g_qkv_txt);
    SYMF(res_i, g_res_i); SYMF(res_t, g_res_t);
    SYMH(mxi_h, g_mxi_h); SYMH(mxi_l, g_mxi_l); SYMH(mxt_h, g_mxt_h); SYMH(mxt_l, g_mxt_l);
    SYMH(wt_h, g_wt_h); SYMH(wt_l, g_wt_l);
    SYMH(qh, g_qh); SYMH(ql, g_ql); SYMH(kh, g_kh); SYMH(kl, g_kl);
    SYMH(vth, g_vth); SYMH(vtl, g_vtl);
    SYMH(aoh, g_aoh); SYMH(aol, g_aol);
    SYMH(hh, g_hh); SYMH(hl, g_hl); SYMH(mh, g_mh); SYMH(ml, g_ml);

    cudaFuncSetAttribute(tgemm<0>, cudaFuncAttributeMaxDynamicSharedMemorySize, TGEMM_SMEM);
    cudaFuncSetAttribute(tgemm<2>, cudaFuncAttributeMaxDynamicSharedMemorySize, TGEMM_SMEM);
    cudaFuncSetAttribute(tgemm<3>, cudaFuncAttributeMaxDynamicSharedMemorySize, TGEMM_SMEM);
    cudaFuncSetAttribute(flash_k, cudaFuncAttributeMaxDynamicSharedMemorySize, FLASH_SMEM);

    dim3 wcb(32, 8);

    // 1. modulation
    silu_k<<<(DD + 255) / 256, 256>>>(vec, sv);
    modmul_k<<<6 * DD / 128, 128>>>(sv, i_mod_w, i_mod_b, mod_i);
    modmul_k<<<6 * DD / 128, 128>>>(sv, t_mod_w, t_mod_b, mod_t);

    // 2. LN1 + modulate -> fp16 hi/lo
    ln_mod_split_k<<<Li, 256>>>(img, mxi_h, mxi_l, mod_i + 0 * DD, mod_i + 1 * DD);
    ln_mod_split_k<<<Lt, 256>>>(txt, mxt_h, mxt_l, mod_t + 0 * DD, mod_t + 1 * DD);

    // 3. QKV GEMMs
    wconv_k<<<dim3(3 * DD / 32, DD / 32), wcb>>>(i_qkv_w, wt_h, wt_l, DD, 3 * DD);
    tgemm<0><<<dim3(3 * DD / 128, Li / 128, 1), 256, TGEMM_SMEM>>>(
        mxi_h, mxi_l, 0, wt_h, wt_l, 0, qkv_i, 0, nullptr, nullptr,
        DD, DD, DD, 3 * DD, 1.0f, nullptr, nullptr, nullptr, 0);
    wconv_k<<<dim3(3 * DD / 32, DD / 32), wcb>>>(t_qkv_w, wt_h, wt_l, DD, 3 * DD);
    tgemm<0><<<dim3(3 * DD / 128, Lt / 128, 1), 256, TGEMM_SMEM>>>(
        mxt_h, mxt_l, 0, wt_h, wt_l, 0, qkv_t, 0, nullptr, nullptr,
        DD, DD, DD, 3 * DD, 1.0f, nullptr, nullptr, nullptr, 0);

    // 4. split + rmsnorm + rope -> fp16 hi/lo
    qkv_prep_k<<<dim3(HH, LL), HD>>>(qkv_t, qkv_i, t_q_s, t_k_s, i_q_s, i_k_s, pe,
                                     qh, ql, kh, kl, vth, vtl);

    // 5. fused flash attention -> aoh/aol
    flash_k<<<dim3(LL / 128, HH), 256, FLASH_SMEM>>>(qh, ql, kh, kl, vth, vtl, aoh, aol);

    // 6. proj + gated residual
    wconv_k<<<dim3(DD / 32, DD / 32), wcb>>>(i_pw, wt_h, wt_l, DD, DD);
    tgemm<2><<<dim3(DD / 128, Li / 128, 1), 256, TGEMM_SMEM>>>(
        aoh + (size_t)Lt * DD, aol + (size_t)Lt * DD, 0, wt_h, wt_l, 0,
        res_i, 0, nullptr, nullptr,
        DD, DD, DD, DD, 1.0f, i_pb, mod_i + 2 * DD, img, DD);
    wconv_k<<<dim3(DD / 32, DD / 32), wcb>>>(t_pw, wt_h, wt_l, DD, DD);
    tgemm<2><<<dim3(DD / 128, Lt / 128, 1), 256, TGEMM_SMEM>>>(
        aoh, aol, 0, wt_h, wt_l, 0, res_t, 0, nullptr, nullptr,
        DD, DD, DD, DD, 1.0f, t_pb, mod_t + 2 * DD, txt, DD);

    // 7. img MLP
    ln_mod_split_k<<<Li, 256>>>(res_i, hh, hl, mod_i + 3 * DD, mod_i + 4 * DD);
    wconv_k<<<dim3(MLPD / 32, DD / 32), wcb>>>(i_w1, wt_h, wt_l, DD, MLPD);
    tgemm<3><<<dim3(MLPD / 128, Li / 128, 1), 256, TGEMM_SMEM>>>(
        hh, hl, 0, wt_h, wt_l, 0, nullptr, 0, mh, ml,
        DD, DD, DD, MLPD, 1.0f, i_b1, nullptr, nullptr, 0);
    wconv_k<<<dim3(DD / 32, MLPD / 32), wcb>>>(i_w2, wt_h, wt_l, MLPD, DD);
    tgemm<2><<<dim3(DD / 128, Li / 128, 1), 256, TGEMM_SMEM>>>(
        mh, ml, 0, wt_h, wt_l, 0, out_img, 0, nullptr, nullptr,
        MLPD, MLPD, MLPD, DD, 1.0f, i_b2, mod_i + 5 * DD, res_i, DD);

    // 8. txt MLP
    ln_mod_split_k<<<Lt, 256>>>(res_t, hh, hl, mod_t + 3 * DD, mod_t + 4 * DD);
    wconv_k<<<dim3(MLPD / 32, DD / 32), wcb>>>(t_w1, wt_h, wt_l, DD, MLPD);
    tgemm<3><<<dim3(MLPD / 128, Lt / 128, 1), 256, TGEMM_SMEM>>>(
        hh, hl, 0, wt_h, wt_l, 0, nullptr, 0, mh, ml,
        DD, DD, DD, MLPD, 1.0f, t_b1, nullptr, nullptr, 0);
    wconv_k<<<dim3(DD / 32, MLPD / 32), wcb>>>(t_w2, wt_h, wt_l, MLPD, DD);
    tgemm<2><<<dim3(DD / 128, Lt / 128, 1), 256, TGEMM_SMEM>>>(
        mh, ml, 0, wt_h, wt_l, 0, out_txt, 0, nullptr, nullptr,
        MLPD, MLPD, MLPD, DD, 1.0f, t_b2, mod_t + 5 * DD, res_t, DD);

    (void)in_sizes; (void)n_in; (void)out_size;
}

// round 9
// speedup vs baseline: 5.6993x; 1.3396x over previous
#include <cuda_runtime.h>
#include <cuda_fp16.h>
#include <math.h>
#include <stdint.h>

#define Lt 256
#define Li 2048
#define LL 2304          // Lt + Li
#define DD 2048
#define HH 16
#define HD 128
#define MLPD 8192
#define EPSF 1e-6f

// ================= helpers =================
__device__ __forceinline__ uint32_t smem_to_u32(const void* p) {
    uint32_t a;
    asm("{ .reg .u64 t; cvta.to.shared.u64 t, %1; cvt.u32.u64 %0, t; }" : "=r"(a) : "l"(p));
    return a;
}
__device__ __forceinline__ void cpa16(uint32_t dst, const void* src) {
    asm volatile("cp.async.cg.shared.global [%0], [%1], 16;" :: "r"(dst), "l"(src));
}
#define CP_COMMIT() asm volatile("cp.async.commit_group;" ::: "memory")
#define CP_WAIT(N)  asm volatile("cp.async.wait_group %0;" :: "n"(N) : "memory")

__device__ __forceinline__ void ldsm_x4(uint32_t addr, uint32_t* r) {
    asm volatile("ldmatrix.sync.aligned.m8n8.x4.shared.b16 {%0,%1,%2,%3}, [%4];"
                 : "=r"(r[0]), "=r"(r[1]), "=r"(r[2]), "=r"(r[3]) : "r"(addr));
}
__device__ __forceinline__ void ldsm_x2(uint32_t addr, uint32_t* r) {
    asm volatile("ldmatrix.sync.aligned.m8n8.x2.shared.b16 {%0,%1}, [%2];"
                 : "=r"(r[0]), "=r"(r[1]) : "r"(addr));
}
__device__ __forceinline__ void mma_fp16(float* d, const uint32_t* a, const uint32_t* b) {
    asm volatile(
        "mma.sync.aligned.m16n8k16.row.col.f32.f16.f16.f32 "
        "{%0,%1,%2,%3}, {%4,%5,%6,%7}, {%8,%9}, {%0,%1,%2,%3};"
        : "+f"(d[0]), "+f"(d[1]), "+f"(d[2]), "+f"(d[3])
        : "r"(a[0]), "r"(a[1]), "r"(a[2]), "r"(a[3]), "r"(b[0]), "r"(b[1]));
}

__device__ __forceinline__ void split2(float x, __half& h, __half& l) {
    h = __float2half_rn(x);
    l = __float2half_rn(x - __half2float(h));
}
__device__ __forceinline__ float gelu_tanh(float x) {
    float x3 = x * x * x;
    return 0.5f * x * (1.0f + tanhf(0.7978845608028654f * (x + 0.044715f * x3)));
}

// ================= scratch (static device globals) =================
__device__ __align__(16) float g_sv[DD];
__device__ __align__(16) float g_mod_img[6 * DD];
__device__ __align__(16) float g_mod_txt[6 * DD];
__device__ __align__(16) __half g_mxi_h[Li * DD];
__device__ __align__(16) __half g_mxi_l[Li * DD];
__device__ __align__(16) __half g_mxt_h[Lt * DD];
__device__ __align__(16) __half g_mxt_l[Lt * DD];
__device__ __align__(16) __half g_wt_h[MLPD * DD];   // transposed rounded weight
__device__ __align__(16) float g_qkv_img[Li * 3 * DD];
__device__ __align__(16) float g_qkv_txt[Lt * 3 * DD];
__device__ __align__(16) __half g_qh[HH * LL * HD];
__device__ __align__(16) __half g_ql[HH * LL * HD];
__device__ __align__(16) __half g_kh[HH * LL * HD];
__device__ __align__(16) __half g_vth[HH * HD * LL]; // V transposed per head [H, HD, LL]
__device__ __align__(16) __half g_vtl[HH * HD * LL];
__device__ __align__(16) __half g_aoh[LL * DD];
__device__ __align__(16) __half g_aol[LL * DD];
__device__ __align__(16) float g_res_i[Li * DD];
__device__ __align__(16) float g_res_t[Lt * DD];
__device__ __align__(16) __half g_hh[Li * DD];
__device__ __align__(16) __half g_hl[Li * DD];
__device__ __align__(16) __half g_mh[(size_t)Li * MLPD];
__device__ __align__(16) __half g_ml[(size_t)Li * MLPD];

// ================= small kernels =================
__global__ void silu_k(const float* __restrict__ vec, float* __restrict__ sv) {
    int i = blockIdx.x * blockDim.x + threadIdx.x;
    if (i < DD) { float x = vec[i]; sv[i] = x / (1.0f + __expf(-x)); }
}

__global__ void modmul_k(const float* __restrict__ sv, const float* __restrict__ W,
                         const float* __restrict__ b, float* __restrict__ out) {
    __shared__ float s[DD];
    for (int i = threadIdx.x; i < DD; i += 128) s[i] = sv[i];
    __syncthreads();
    int j = blockIdx.x * 128 + threadIdx.x;
    float acc = 0.0f;
    const float* wp = W + j;
    for (int d = 0; d < DD; d++) acc += s[d] * wp[(size_t)d * (6 * DD)];
    out[j] = acc + b[j];
}

// y_hi/y_lo = split((1+sc)*LN(x) + sh)
__global__ void ln_mod_split_k(const float* __restrict__ x,
                               __half* __restrict__ yh, __half* __restrict__ yl,
                               const float* __restrict__ sh, const float* __restrict__ sc) {
    int row = blockIdx.x;
    const float* px = x + (size_t)row * DD;
    __shared__ float red[256];
    int tid = threadIdx.x;
    float v[8];
    float s = 0.0f;
#pragma unroll
    for (int i = 0; i < 8; i++) { v[i] = px[tid + i * 256]; s += v[i]; }
    red[tid] = s; __syncthreads();
    for (int o = 128; o > 0; o >>= 1) { if (tid < o) red[tid] += red[tid + o]; __syncthreads(); }
    float mu = red[0] * (1.0f / DD);
    __syncthreads();
    float ss = 0.0f;
#pragma unroll
    for (int i = 0; i < 8; i++) { float d = v[i] - mu; ss += d * d; }
    red[tid] = ss; __syncthreads();
    for (int o = 128; o > 0; o >>= 1) { if (tid < o) red[tid] += red[tid + o]; __syncthreads(); }
    float r = rsqrtf(red[0] * (1.0f / DD) + EPSF);
#pragma unroll
    for (int i = 0; i < 8; i++) {
        int c = tid + i * 256;
        float y = (1.0f + sc[c]) * ((v[i] - mu) * r) + sh[c];
        __half h, l; split2(y, h, l);
        yh[(size_t)row * DD + c] = h;
        yl[(size_t)row * DD + c] = l;
    }
}

// transpose + round: W[K,N] fp32 -> Wt [N,K] fp16
__global__ void wconv_k(const float* __restrict__ W,
                        __half* __restrict__ Wh, int Kd, int Nd) {
    __shared__ float t[32][33];
    int n = blockIdx.x * 32 + threadIdx.x;
#pragma unroll
    for (int i = 0; i < 4; i++) {
        int k = blockIdx.y * 32 + threadIdx.y + i * 8;
        t[threadIdx.y + i * 8][threadIdx.x] = W[(size_t)k * Nd + n];
    }
    __syncthreads();
    int k2 = blockIdx.y * 32 + threadIdx.x;
#pragma unroll
    for (int i = 0; i < 4; i++) {
        int n2 = blockIdx.x * 32 + threadIdx.y + i * 8;
        Wh[(size_t)n2 * Kd + k2] = __float2half_rn(t[threadIdx.x][threadIdx.y + i * 8]);
    }
}

// split qkv, rmsnorm(q,k)*scale, rope(q,k); q split hi/lo, k rounded, v split (transposed)
__global__ void qkv_prep_k(const float* __restrict__ qkv_txt, const float* __restrict__ qkv_img,
                           const float* __restrict__ tq_s, const float* __restrict__ tk_s,
                           const float* __restrict__ iq_s, const float* __restrict__ ik_s,
                           const float* __restrict__ pe,
                           __half* __restrict__ qh, __half* __restrict__ ql,
                           __half* __restrict__ kh,
                           __half* __restrict__ vth, __half* __restrict__ vtl) {
    int h = blockIdx.x;
    int pos = blockIdx.y;
    int d = threadIdx.x;
    const float* src; int l; const float* qs; const float* ks;
    if (pos < Lt) { src = qkv_txt; l = pos;      qs = tq_s; ks = tk_s; }
    else          { src = qkv_img; l = pos - Lt; qs = iq_s; ks = ik_s; }
    const float* base = src + (size_t)l * (3 * DD) + h * HD;
    float qv = base[d];
    float kv = base[DD + d];
    float vv = base[2 * DD + d];

    __shared__ float sq[HD], sk[HD], red[8];
    float q2 = qv * qv, k2 = kv * kv;
#pragma unroll
    for (int o = 16; o > 0; o >>= 1) {
        q2 += __shfl_xor_sync(0xFFFFFFFFu, q2, o);
        k2 += __shfl_xor_sync(0xFFFFFFFFu, k2, o);
    }
    int w = d >> 5;
    if ((d & 31) == 0) { red[w] = q2; red[4 + w] = k2; }
    __syncthreads();
    float qss = red[0] + red[1] + red[2] + red[3];
    float kss = red[4] + red[5] + red[6] + red[7];
    float qn = qv * rsqrtf(qss * (1.0f / HD) + EPSF) * qs[d];
    float kn = kv * rsqrtf(kss * (1.0f / HD) + EPSF) * ks[d];
    sq[d] = qn; sk[d] = kn;
    __syncthreads();
    int i = d >> 1, j = d & 1;
    const float* pp = pe + (((size_t)pos * 64 + i) * 4 + j * 2);
    float p0 = pp[0], p1 = pp[1];
    float rq = p0 * sq[2 * i] + p1 * sq[2 * i + 1];
    float rk = p0 * sk[2 * i] + p1 * sk[2 * i + 1];
    size_t o = ((size_t)h * LL + pos) * HD + d;
    __half a, b;
    split2(rq, a, b); qh[o] = a; ql[o] = b;
    kh[o] = __float2half_rn(rk);
    size_t ov = ((size_t)h * HD + d) * LL + pos;
    split2(vv, a, b); vth[ov] = a; vtl[ov] = b;
}

// ================= fused flash attention =================
// Per CTA: one head, 128 Q rows. KV chunks of 64, double-buffered cp.async.
// S = (qh+ql)·kh (2 mma), P rounded fp16, O += pH·(vh+vl) (2 mma).
#define FCHUNK 64
#define NCHUNK (LL / FCHUNK)       // 36
#define F_QROW 272                 // 128 cols fp16 + 16B pad
#define F_QSZ  (128 * F_QROW)      // 34816 per array
#define F_KROW 272
#define F_KSZ  (64 * F_KROW)       // 17408
#define F_VROW 144                 // 64 cols fp16 + 16B pad
#define F_VSZ  (128 * F_VROW)      // 18432 per array
#define F_STG0 (2 * F_QSZ)         // 69632
#define F_STGSZ (F_KSZ + 2 * F_VSZ)      // 54272
#define FLASH_SMEM (F_STG0 + 2 * F_STGSZ) // 178176

__global__ __launch_bounds__(256, 1) void flash_k(
    const __half* __restrict__ qhg, const __half* __restrict__ qlg,
    const __half* __restrict__ khg,
    const __half* __restrict__ vthg, const __half* __restrict__ vtlg,
    __half* __restrict__ aoh, __half* __restrict__ aol) {
    extern __shared__ char smem[];
    uint32_t sb = smem_to_u32(smem);
    int tid = threadIdx.x, wid = tid >> 5, lane = tid & 31;
    int h = blockIdx.y, qt = blockIdx.x;
    const float iscale = 0.08838834764831845f; // 1/sqrt(128)

    // ---- load Q tile (once) ----
#pragma unroll
    for (int i = 0; i < 8; i++) {
        int u = tid + i * 256;          // 0..2047
        int row = u >> 4, cu = u & 15;
        size_t go = ((size_t)h * LL + qt * 128 + row) * HD + cu * 8;
        cpa16(sb + row * F_QROW + cu * 16, qhg + go);
        cpa16(sb + F_QSZ + row * F_QROW + cu * 16, qlg + go);
    }
    CP_COMMIT();

    // ---- prefetch chunk 0 ----
    {
        uint32_t st = sb + F_STG0;
#pragma unroll
        for (int i = 0; i < 4; i++) {
            int u = tid + i * 256;      // 0..1023
            int row = u >> 4, cu = u & 15;
            size_t go = ((size_t)h * LL + row) * HD + cu * 8;
            cpa16(st + row * F_KROW + cu * 16, khg + go);
            int vr = u >> 3, vc = u & 7;
            size_t gv = ((size_t)h * HD + vr) * LL + vc * 8;
            cpa16(st + F_KSZ + vr * F_VROW + vc * 16, vthg + gv);
            cpa16(st + F_KSZ + F_VSZ + vr * F_VROW + vc * 16, vtlg + gv);
        }
        CP_COMMIT();
    }

    float o[16][4];
#pragma unroll
    for (int i = 0; i < 16; i++)
#pragma unroll
        for (int f = 0; f < 4; f++) o[i][f] = 0.0f;
    float m0 = -1e30f, m1 = -1e30f, l0 = 0.0f, l1 = 0.0f;

    uint32_t qa_base = sb + (wid * 16 + (lane & 15)) * F_QROW + ((lane >> 4) * 16);

    for (int j = 0; j < NCHUNK; j++) {
        CP_WAIT(0);
        __syncthreads();
        if (j + 1 < NCHUNK) {
            int ln = (j + 1) * FCHUNK;
            uint32_t st = sb + F_STG0 + ((j + 1) & 1) * F_STGSZ;
#pragma unroll
            for (int i = 0; i < 4; i++) {
                int u = tid + i * 256;
                int row = u >> 4, cu = u & 15;
                size_t go = ((size_t)h * LL + ln + row) * HD + cu * 8;
                cpa16(st + row * F_KROW + cu * 16, khg + go);
                int vr = u >> 3, vc = u & 7;
                size_t gv = ((size_t)h * HD + vr) * LL + ln + vc * 8;
                cpa16(st + F_KSZ + vr * F_VROW + vc * 16, vthg + gv);
                cpa16(st + F_KSZ + F_VSZ + vr * F_VROW + vc * 16, vtlg + gv);
            }
            CP_COMMIT();
        }

        uint32_t st = sb + F_STG0 + (j & 1) * F_STGSZ;

        // ---- S = Q @ K^T ----
        float S[8][4];
#pragma unroll
        for (int i = 0; i < 8; i++)
#pragma unroll
            for (int f = 0; f < 4; f++) S[i][f] = 0.0f;
#pragma unroll
        for (int kk = 0; kk < 8; kk++) {
            uint32_t aH[4], aL[4];
            uint32_t qa = qa_base + kk * 32;
            ldsm_x4(qa, aH);
            ldsm_x4(qa + F_QSZ, aL);
#pragma unroll
            for (int ni = 0; ni < 8; ni++) {
                uint32_t bH[2];
                uint32_t ka = st + (ni * 8 + (lane & 7)) * F_KROW + ((lane >> 3) & 1) * 16 + kk * 32;
                ldsm_x2(ka, bH);
                mma_fp16(S[ni], aH, bH);
                mma_fp16(S[ni], aL, bH);
            }
        }

        // ---- online softmax ----
        float rm0 = -1e30f, rm1 = -1e30f;
#pragma unroll
        for (int ni = 0; ni < 8; ni++) {
            rm0 = fmaxf(rm0, fmaxf(S[ni][0], S[ni][1]));
            rm1 = fmaxf(rm1, fmaxf(S[ni][2], S[ni][3]));
        }
        rm0 = fmaxf(rm0, __shfl_xor_sync(0xFFFFFFFFu, rm0, 1));
        rm0 = fmaxf(rm0, __shfl_xor_sync(0xFFFFFFFFu, rm0, 2));
        rm1 = fmaxf(rm1, __shfl_xor_sync(0xFFFFFFFFu, rm1, 1));
        rm1 = fmaxf(rm1, __shfl_xor_sync(0xFFFFFFFFu, rm1, 2));
        float mn0 = fmaxf(m0, rm0), mn1 = fmaxf(m1, rm1);
        float f0 = __expf((m0 - mn0) * iscale);
        float f1 = __expf((m1 - mn1) * iscale);
        m0 = mn0; m1 = mn1;
        float rs0 = 0.0f, rs1 = 0.0f;
#pragma unroll
        for (int ni = 0; ni < 8; ni++) {
            S[ni][0] = __expf((S[ni][0] - mn0) * iscale);
            S[ni][1] = __expf((S[ni][1] - mn0) * iscale);
            S[ni][2] = __expf((S[ni][2] - mn1) * iscale);
            S[ni][3] = __expf((S[ni][3] - mn1) * iscale);
            rs0 += S[ni][0] + S[ni][1];
            rs1 += S[ni][2] + S[ni][3];
        }
        rs0 += __shfl_xor_sync(0xFFFFFFFFu, rs0, 1);
        rs0 += __shfl_xor_sync(0xFFFFFFFFu, rs0, 2);
        rs1 += __shfl_xor_sync(0xFFFFFFFFu, rs1, 1);
        rs1 += __shfl_xor_sync(0xFFFFFFFFu, rs1, 2);
        l0 = l0 * f0 + rs0;
        l1 = l1 * f1 + rs1;
#pragma unroll
        for (int ni = 0; ni < 16; ni++) {
            o[ni][0] *= f0; o[ni][1] *= f0;
            o[ni][2] *= f1; o[ni][3] *= f1;
        }

        // ---- O += P @ V ----
#pragma unroll
        for (int kf = 0; kf < 4; kf++) {
            uint32_t pH[4];
            {
                float* c0 = S[2 * kf];
                float* c1 = S[2 * kf + 1];
                __half2 t;
                t = __floats2half2_rn(c0[0], c0[1]); pH[0] = *(uint32_t*)&t;
                t = __floats2half2_rn(c0[2], c0[3]); pH[1] = *(uint32_t*)&t;
                t = __floats2half2_rn(c1[0], c1[1]); pH[2] = *(uint32_t*)&t;
                t = __floats2half2_rn(c1[2], c1[3]); pH[3] = *(uint32_t*)&t;
            }
#pragma unroll
            for (int ni = 0; ni < 16; ni++) {
                uint32_t bH[2], bL[2];
                uint32_t va = st + F_KSZ + (ni * 8 + (lane & 7)) * F_VROW +
                              ((lane >> 3) & 1) * 16 + kf * 32;
                ldsm_x2(va, bH);
                ldsm_x2(va + F_VSZ, bL);
                mma_fp16(o[ni], pH, bH);
                mma_fp16(o[ni], pH, bL);
            }
        }
        __syncthreads();
    }

    // ---- normalize + write out split hi/lo ----
    float inv0 = 1.0f / l0, inv1 = 1.0f / l1;
    int row0 = qt * 128 + wid * 16 + (lane >> 2);
    int row1 = row0 + 8;
#pragma unroll
    for (int ni = 0; ni < 16; ni++) {
        int col = h * HD + ni * 8 + (lane & 3) * 2;
        float a0 = o[ni][0] * inv0, a1 = o[ni][1] * inv0;
        float b0 = o[ni][2] * inv1, b1 = o[ni][3] * inv1;
        __half2 h0 = __floats2half2_rn(a0, a1);
        __half2 l0v; { float x = a0 - __low2float(h0), y = a1 - __high2float(h0); l0v = __floats2half2_rn(x, y); }
        __half2 h1 = __floats2half2_rn(b0, b1);
        __half2 l1v; { float x = b0 - __low2float(h1), y = b1 - __high2float(h1); l1v = __floats2half2_rn(x, y); }
        *(__half2*)&aoh[(size_t)row0 * DD + col] = h0;
        *(__half2*)&aol[(size_t)row0 * DD + col] = l0v;
        *(__half2*)&aoh[(size_t)row1 * DD + col] = h1;
        *(__half2*)&aol[(size_t)row1 * DD + col] = l1v;
    }
}

// ================= HMMA (mma.sync fp16) GEMM =================
// C[M,N] = epi( (Ah+Al)[M,K] @ Bh[N,K]^T ), 2-product split (A exact, B rounded), fp32 accum.
// CTA tile 128x128, BK=32. 8 warps (2x4), warp tile 64x32.
#define SROW 80
#define ARRB (128 * SROW)
#define STAGEB (3 * ARRB)
#define TGEMM_SMEM (2 * STAGEB)    // 61440

template <int EPI>
__global__ __launch_bounds__(256, 1) void tgemm(
    const __half* __restrict__ Ah, const __half* __restrict__ Al, long long sAz,
    const __half* __restrict__ Bh, long long sBz,
    float* __restrict__ C, long long sCz,
    __half* __restrict__ Chi, __half* __restrict__ Clo,
    int K, int lda, int ldb, int ldc, float alpha,
    const float* __restrict__ bias, const float* __restrict__ gate,
    const float* __restrict__ res, int ldres) {
    extern __shared__ char smem[];
    uint32_t sb = smem_to_u32(smem);
    int tid = threadIdx.x, wid = tid >> 5, lane = tid & 31;
    int warpM = wid >> 2, warpN = wid & 3;
    int m0 = blockIdx.y * 128, n0 = blockIdx.x * 128;
    int z = blockIdx.z;
    Ah += (size_t)z * sAz; Al += (size_t)z * sAz;
    Bh += (size_t)z * sBz;
    if (C)   C   += (size_t)z * sCz;
    if (Chi) { Chi += (size_t)z * sCz; Clo += (size_t)z * sCz; }

    const __half* g0 = Ah + (size_t)m0 * lda;
    const __half* g1 = Al + (size_t)m0 * lda;
    const __half* g2 = Bh + (size_t)n0 * ldb;

    int r0 = tid >> 2, q0 = tid & 3;
    int r1 = (tid + 256) >> 2, q1 = q0;
    uint32_t d00 = sb + r0 * SROW + q0 * 16;
    uint32_t d01 = sb + r1 * SROW + q1 * 16;

    float acc[4][4][4];
#pragma unroll
    for (int i = 0; i < 4; i++)
#pragma unroll
        for (int j = 0; j < 4; j++)
#pragma unroll
            for (int f = 0; f < 4; f++) acc[i][j][f] = 0.0f;

    int nit = K / 32;

    {
        cpa16(d00 + 0 * ARRB, g0 + (size_t)r0 * lda + q0 * 8);
        cpa16(d01 + 0 * ARRB, g0 + (size_t)r1 * lda + q1 * 8);
        cpa16(d00 + 1 * ARRB, g1 + (size_t)r0 * lda + q0 * 8);
        cpa16(d01 + 1 * ARRB, g1 + (size_t)r1 * lda + q1 * 8);
        cpa16(d00 + 2 * ARRB, g2 + (size_t)r0 * ldb + q0 * 8);
        cpa16(d01 + 2 * ARRB, g2 + (size_t)r1 * ldb + q1 * 8);
        CP_COMMIT();
    }

    uint32_t a_base = sb + (warpM * 64 + (lane & 15)) * SROW + ((lane >> 4) * 16);
    uint32_t b_base = sb + 2 * ARRB + (warpN * 32 + (lane & 7)) * SROW + (((lane >> 3) & 1) * 16);

    for (int it = 0; it < nit; it++) {
        bool pf = (it + 1) < nit;
        if (pf) {
            int k0 = (it + 1) * 32;
            uint32_t st = ((it + 1) & 1) * STAGEB;
            cpa16(d00 + st + 0 * ARRB, g0 + (size_t)r0 * lda + k0 + q0 * 8);
            cpa16(d01 + st + 0 * ARRB, g0 + (size_t)r1 * lda + k0 + q1 * 8);
            cpa16(d00 + st + 1 * ARRB, g1 + (size_t)r0 * lda + k0 + q0 * 8);
            cpa16(d01 + st + 1 * ARRB, g1 + (size_t)r1 * lda + k0 + q1 * 8);
            cpa16(d00 + st + 2 * ARRB, g2 + (size_t)r0 * ldb + k0 + q0 * 8);
            cpa16(d01 + st + 2 * ARRB, g2 + (size_t)r1 * ldb + k0 + q1 * 8);
            CP_COMMIT();
            CP_WAIT(1);
        } else {
            CP_WAIT(0);
        }
        __syncthreads();

        uint32_t st = (it & 1) * STAGEB;
        uint32_t ab = a_base + st;
        uint32_t bb = b_base + st;
#pragma unroll
        for (int kk = 0; kk < 2; kk++) {
            int kb = kk * 32;
            uint32_t ah[4][4], al[4][4];
#pragma unroll
            for (int mi = 0; mi < 4; mi++) {
                ldsm_x4(ab + mi * (16 * SROW) + kb, ah[mi]);
                ldsm_x4(ab + ARRB + mi * (16 * SROW) + kb, al[mi]);
            }
#pragma unroll
            for (int ni = 0; ni < 4; ni++) {
                uint32_t bh[2];
                ldsm_x2(bb + ni * (8 * SROW) + kb, bh);
#pragma unroll
                for (int mi = 0; mi < 4; mi++) {
                    mma_fp16(acc[mi][ni], ah[mi], bh);
                    mma_fp16(acc[mi][ni], al[mi], bh);
                }
            }
        }
        __syncthreads();
    }

    int rbase = m0 + warpM * 64 + (lane >> 2);
    int cbase = n0 + warpN * 32 + (lane & 3) * 2;
#pragma unroll
    for (int mi = 0; mi < 4; mi++) {
#pragma unroll
        for (int ni = 0; ni < 4; ni++) {
            int col = cbase + ni * 8;
#pragma unroll
            for (int hf = 0; hf < 2; hf++) {
                int row = rbase + mi * 16 + hf * 8;
                float v0 = acc[mi][ni][hf * 2 + 0];
                float v1 = acc[mi][ni][hf * 2 + 1];
                if (EPI == 0) {
                    float2 oo; oo.x = alpha * v0; oo.y = alpha * v1;
                    *(float2*)&C[(size_t)row * ldc + col] = oo;
                } else if (EPI == 2) {
                    float2 oo;
                    oo.x = res[(size_t)row * ldres + col + 0] + gate[col + 0] * (v0 + bias[col + 0]);
                    oo.y = res[(size_t)row * ldres + col + 1] + gate[col + 1] * (v1 + bias[col + 1]);
                    *(float2*)&C[(size_t)row * ldc + col] = oo;
                } else { // EPI 3
                    float gg0 = gelu_tanh(v0 + bias[col]);
                    float gg1 = gelu_tanh(v1 + bias[col + 1]);
                    __half2 hp = __floats2half2_rn(gg0, gg1);
                    float rr0 = gg0 - __low2float(hp), rr1 = gg1 - __high2float(hp);
                    __half2 lp = __floats2half2_rn(rr0, rr1);
                    *(__half2*)&Chi[(size_t)row * ldc + col] = hp;
                    *(__half2*)&Clo[(size_t)row * ldc + col] = lp;
                }
            }
        }
    }
}

// ================= host side =================
#define SYMF(p, s) do { void* _t = nullptr; cudaGetSymbolAddress(&_t, s); (p) = (float*)_t; } while (0)
#define SYMH(p, s) do { void* _t = nullptr; cudaGetSymbolAddress(&_t, s); (p) = (__half*)_t; } while (0)

extern "C" void kernel_launch(void* const* d_in, const int* in_sizes, int n_in,
                              void* d_out, int out_size) {
    const float* img     = (const float*)d_in[0];
    const float* txt     = (const float*)d_in[1];
    const float* vec     = (const float*)d_in[2];
    const float* pe      = (const float*)d_in[3];
    const float* i_mod_w = (const float*)d_in[4];
    const float* i_mod_b = (const float*)d_in[5];
    const float* i_qkv_w = (const float*)d_in[6];
    const float* i_q_s   = (const float*)d_in[7];
    const float* i_k_s   = (const float*)d_in[8];
    const float* i_pw    = (const float*)d_in[9];
    const float* i_pb    = (const float*)d_in[10];
    const float* i_w1    = (const float*)d_in[11];
    const float* i_b1    = (const float*)d_in[12];
    const float* i_w2    = (const float*)d_in[13];
    const float* i_b2    = (const float*)d_in[14];
    const float* t_mod_w = (const float*)d_in[15];
    const float* t_mod_b = (const float*)d_in[16];
    const float* t_qkv_w = (const float*)d_in[17];
    const float* t_q_s   = (const float*)d_in[18];
    const float* t_k_s   = (const float*)d_in[19];
    const float* t_pw    = (const float*)d_in[20];
    const float* t_pb    = (const float*)d_in[21];
    const float* t_w1    = (const float*)d_in[22];
    const float* t_b1    = (const float*)d_in[23];
    const float* t_w2    = (const float*)d_in[24];
    const float* t_b2    = (const float*)d_in[25];

    float* out_img = (float*)d_out;
    float* out_txt = out_img + (size_t)Li * DD;

    float *sv, *mod_i, *mod_t, *qkv_i, *qkv_t, *res_i, *res_t;
    __half *mxi_h, *mxi_l, *mxt_h, *mxt_l, *wt_h;
    __half *qh, *ql, *kh, *vth, *vtl, *aoh, *aol, *hh, *hl, *mh, *ml;
    SYMF(sv, g_sv); SYMF(mod_i, g_mod_img); SYMF(mod_t, g_mod_txt);
    SYMF(qkv_i, g_qkv_img); SYMF(qkv_t, g_qkv_txt);
    SYMF(res_i, g_res_i); SYMF(res_t, g_res_t);
    SYMH(mxi_h, g_mxi_h); SYMH(mxi_l, g_mxi_l); SYMH(mxt_h, g_mxt_h); SYMH(mxt_l, g_mxt_l);
    SYMH(wt_h, g_wt_h);
    SYMH(qh, g_qh); SYMH(ql, g_ql); SYMH(kh, g_kh);
    SYMH(vth, g_vth); SYMH(vtl, g_vtl);
    SYMH(aoh, g_aoh); SYMH(aol, g_aol);
    SYMH(hh, g_hh); SYMH(hl, g_hl); SYMH(mh, g_mh); SYMH(ml, g_ml);

    cudaFuncSetAttribute(tgemm<0>, cudaFuncAttributeMaxDynamicSharedMemorySize, TGEMM_SMEM);
    cudaFuncSetAttribute(tgemm<2>, cudaFuncAttributeMaxDynamicSharedMemorySize, TGEMM_SMEM);
    cudaFuncSetAttribute(tgemm<3>, cudaFuncAttributeMaxDynamicSharedMemorySize, TGEMM_SMEM);
    cudaFuncSetAttribute(flash_k, cudaFuncAttributeMaxDynamicSharedMemorySize, FLASH_SMEM);

    dim3 wcb(32, 8);

    // 1. modulation
    silu_k<<<(DD + 255) / 256, 256>>>(vec, sv);
    modmul_k<<<6 * DD / 128, 128>>>(sv, i_mod_w, i_mod_b, mod_i);
    modmul_k<<<6 * DD / 128, 128>>>(sv, t_mod_w, t_mod_b, mod_t);

    // 2. LN1 + modulate -> fp16 hi/lo
    ln_mod_split_k<<<Li, 256>>>(img, mxi_h, mxi_l, mod_i + 0 * DD, mod_i + 1 * DD);
    ln_mod_split_k<<<Lt, 256>>>(txt, mxt_h, mxt_l, mod_t + 0 * DD, mod_t + 1 * DD);

    // 3. QKV GEMMs
    wconv_k<<<dim3(3 * DD / 32, DD / 32), wcb>>>(i_qkv_w, wt_h, DD, 3 * DD);
    tgemm<0><<<dim3(3 * DD / 128, Li / 128, 1), 256, TGEMM_SMEM>>>(
        mxi_h, mxi_l, 0, wt_h, 0, qkv_i, 0, nullptr, nullptr,
        DD, DD, DD, 3 * DD, 1.0f, nullptr, nullptr, nullptr, 0);
    wconv_k<<<dim3(3 * DD / 32, DD / 32), wcb>>>(t_qkv_w, wt_h, DD, 3 * DD);
    tgemm<0><<<dim3(3 * DD / 128, Lt / 128, 1), 256, TGEMM_SMEM>>>(
        mxt_h, mxt_l, 0, wt_h, 0, qkv_t, 0, nullptr, nullptr,
        DD, DD, DD, 3 * DD, 1.0f, nullptr, nullptr, nullptr, 0);

    // 4. split + rmsnorm + rope
    qkv_prep_k<<<dim3(HH, LL), HD>>>(qkv_t, qkv_i, t_q_s, t_k_s, i_q_s, i_k_s, pe,
                                     qh, ql, kh, vth, vtl);

    // 5. fused flash attention -> aoh/aol
    flash_k<<<dim3(LL / 128, HH), 256, FLASH_SMEM>>>(qh, ql, kh, vth, vtl, aoh, aol);

    // 6. proj + gated residual
    wconv_k<<<dim3(DD / 32, DD / 32), wcb>>>(i_pw, wt_h, DD, DD);
    tgemm<2><<<dim3(DD / 128, Li / 128, 1), 256, TGEMM_SMEM>>>(
        aoh + (size_t)Lt * DD, aol + (size_t)Lt * DD, 0, wt_h, 0,
        res_i, 0, nullptr, nullptr,
        DD, DD, DD, DD, 1.0f, i_pb, mod_i + 2 * DD, img, DD);
    wconv_k<<<dim3(DD / 32, DD / 32), wcb>>>(t_pw, wt_h, DD, DD);
    tgemm<2><<<dim3(DD / 128, Lt / 128, 1), 256, TGEMM_SMEM>>>(
        aoh, aol, 0, wt_h, 0, res_t, 0, nullptr, nullptr,
        DD, DD, DD, DD, 1.0f, t_pb, mod_t + 2 * DD, txt, DD);

    // 7. img MLP
    ln_mod_split_k<<<Li, 256>>>(res_i, hh, hl, mod_i + 3 * DD, mod_i + 4 * DD);
    wconv_k<<<dim3(MLPD / 32, DD / 32), wcb>>>(i_w1, wt_h, DD, MLPD);
    tgemm<3><<<dim3(MLPD / 128, Li / 128, 1), 256, TGEMM_SMEM>>>(
        hh, hl, 0, wt_h, 0, nullptr, 0, mh, ml,
        DD, DD, DD, MLPD, 1.0f, i_b1, nullptr, nullptr, 0);
    wconv_k<<<dim3(DD / 32, MLPD / 32), wcb>>>(i_w2, wt_h, MLPD, DD);
    tgemm<2><<<dim3(DD / 128, Li / 128, 1), 256, TGEMM_SMEM>>>(
        mh, ml, 0, wt_h, 0, out_img, 0, nullptr, nullptr,
        MLPD, MLPD, MLPD, DD, 1.0f, i_b2, mod_i + 5 * DD, res_i, DD);

    // 8. txt MLP
    ln_mod_split_k<<<Lt, 256>>>(res_t, hh, hl, mod_t + 3 * DD, mod_t + 4 * DD);
    wconv_k<<<dim3(MLPD / 32, DD / 32), wcb>>>(t_w1, wt_h, DD, MLPD);
    tgemm<3><<<dim3(MLPD / 128, Lt / 128, 1), 256, TGEMM_SMEM>>>(
        hh, hl, 0, wt_h, 0, nullptr, 0, mh, ml,
        DD, DD, DD, MLPD, 1.0f, t_b1, nullptr, nullptr, 0);
    wconv_k<<<dim3(DD / 32, MLPD / 32), wcb>>>(t_w2, wt_h, MLPD, DD);
    tgemm<2><<<dim3(DD / 128, Lt / 128, 1), 256, TGEMM_SMEM>>>(
        mh, ml, 0, wt_h, 0, out_txt, 0, nullptr, nullptr,
        MLPD, MLPD, MLPD, DD, 1.0f, t_b2, mod_t + 5 * DD, res_t, DD);

    (void)in_sizes; (void)n_in; (void)out_size;
}